// round 13
// baseline (speedup 1.0000x reference)
#include <cuda_runtime.h>
#include <cuda_bf16.h>
#include <cstdint>

#define NROWS 8192
#define DIM   16
#define NCT   64
#define NTRI  (NCT * (NCT + 1) / 2)   // 2080
#define LOG2E 1.4426950408889634f

typedef unsigned long long ull;

// ---- device scratch (static, no allocation) ----
__device__ float g_P1[NROWS * NCT];    // ref pass: sum K
__device__ float g_P2[NROWS * NCT];    // ref pass: sum K*Dref
__device__ float g_P1x[NROWS * NCT];   // x pass: sum K
__device__ float g_P2x[NROWS * NCT];   // x pass: sum K*Dref
__device__ float g_Dref[NROWS];
__device__ float g_bcol[NROWS];
__device__ float g_arow[NROWS];

__device__ __forceinline__ float ex2_approx(float x) {
    float r; asm("ex2.approx.f32 %0, %1;" : "=f"(r) : "f"(x)); return r;
}
__device__ __forceinline__ float softplus_f(float x) { return log1pf(expf(x)); }

__device__ __forceinline__ void mma16816(float& d0, float& d1, float& d2, float& d3,
                                         uint32_t a0, uint32_t a1, uint32_t a2, uint32_t a3,
                                         uint32_t b0, uint32_t b1) {
    asm volatile(
        "mma.sync.aligned.m16n8k16.row.col.f32.bf16.bf16.f32 "
        "{%0,%1,%2,%3}, {%4,%5,%6,%7}, {%8,%9}, {%0,%1,%2,%3};"
        : "+f"(d0), "+f"(d1), "+f"(d2), "+f"(d3)
        : "r"(a0), "r"(a1), "r"(a2), "r"(a3), "r"(b0), "r"(b1));
}

// ---- packed f32x2 helpers (used for d-init and X_WRITE stores only) ----
__device__ __forceinline__ ull dup2(float x) {
    ull r; asm("mov.b64 %0, {%1, %1};" : "=l"(r) : "f"(x)); return r;
}
__device__ __forceinline__ ull packf2(float lo, float hi) {
    ull r; asm("mov.b64 %0, {%1, %2};" : "=l"(r) : "f"(lo), "f"(hi)); return r;
}
__device__ __forceinline__ void unpackf2(ull v, float& lo, float& hi) {
    asm("mov.b64 {%0, %1}, %2;" : "=f"(lo), "=f"(hi) : "l"(v));
}
__device__ __forceinline__ ull add2p(ull a, ull b) {
    ull d; asm("add.rn.f32x2 %0, %1, %2;" : "=l"(d) : "l"(a), "l"(b)); return d;
}
__device__ __forceinline__ ull mul2p(ull a, ull b) {
    ull d; asm("mul.rn.f32x2 %0, %1, %2;" : "=l"(d) : "l"(a), "l"(b)); return d;
}

// scalar accumulate with FFMA-imm (rt_SMSP = 1)
__device__ __forceinline__ void acc1(float& s, float k) { s = fmaf(k, 1.0f, s); }

// pack two floats into (hi bf16x2, lo bf16x2)
__device__ __forceinline__ uint2 pack_hilo(float x0, float x1) {
    uint32_t hw, lw;
    asm("cvt.rn.bf16x2.f32 %0, %2, %1;" : "=r"(hw) : "f"(x0), "f"(x1));
    float h0 = __bfloat162float(__ushort_as_bfloat16((unsigned short)(hw & 0xffffu)));
    float h1 = __bfloat162float(__ushort_as_bfloat16((unsigned short)(hw >> 16)));
    float l0 = x0 - h0;
    float l1 = x1 - h1;
    asm("cvt.rn.bf16x2.f32 %0, %2, %1;" : "=r"(lw) : "f"(l0), "f"(l1));
    uint2 r; r.x = hw; r.y = lw;
    return r;
}

#define M_REF_SUM 0
#define M_REF_W   1
#define M_X_SUM   2
#define M_X_WRITE 3

// ===========================================================================
// SQUARE symmetric kernel (ref passes) — scalar FFMA accumulation
// ===========================================================================
template <int MODE>
__global__ void __launch_bounds__(256, 4)
k_eval_sq(const float* __restrict__ A,
          const float* __restrict__ B,
          const float* __restrict__ lep) {
    __shared__ uint4 sAf[128][4];
    __shared__ uint4 sBf[16][32];
    __shared__ float sU[128], sV[128], sW[128], sWa[128];
    __shared__ float sCol[8][128];

    int bx, by;
    {
        int l = blockIdx.x;
        bx = (int)((sqrtf(8.0f * (float)l + 1.0f) - 1.0f) * 0.5f);
        while ((bx * (bx + 1)) / 2 > l) bx--;
        while (((bx + 1) * (bx + 2)) / 2 <= l) bx++;
        by = l - (bx * (bx + 1)) / 2;
    }
    const bool offdiag = (by != bx);

    const int tid = threadIdx.x;
    const int w = tid >> 5;
    const int lane = tid & 31;
    const int g = lane >> 2;
    const int kq = lane & 3;
    const int rb = by * 128;
    const int cb = bx * 128;

    const float eps = softplus_f(__ldg(lep));
    const float twoc2 = 2.0f * LOG2E / (4.0f * eps);
    const float sc = sqrtf(twoc2);

    {
        const int r = tid & 127;
        const bool isA = (tid < 128);
        const float4* s4 = reinterpret_cast<const float4*>(
            (isA ? A + (size_t)(rb + r) * DIM : B + (size_t)(cb + r) * DIM));
        float v[16]; float nrm = 0.0f;
#pragma unroll
        for (int q = 0; q < 4; q++) {
            float4 t = s4[q];
            v[4 * q] = t.x * sc; v[4 * q + 1] = t.y * sc;
            v[4 * q + 2] = t.z * sc; v[4 * q + 3] = t.w * sc;
            nrm += v[4 * q] * v[4 * q] + v[4 * q + 1] * v[4 * q + 1] +
                   v[4 * q + 2] * v[4 * q + 2] + v[4 * q + 3] * v[4 * q + 3];
        }
        uint2 p[8];
#pragma unroll
        for (int kp = 0; kp < 8; kp++) p[kp] = pack_hilo(v[2 * kp], v[2 * kp + 1]);
        if (isA) {
#pragma unroll
            for (int q = 0; q < 4; q++)
                sAf[r][q] = make_uint4(p[q].x, p[q].y, p[q + 4].x, p[q + 4].y);
            sU[r] = -0.5f * nrm;
            if (MODE == M_REF_W) sWa[r] = g_Dref[rb + r];
        } else {
            const int bg = r & 7;
            const int bc8 = r >> 3;
#pragma unroll
            for (int q = 0; q < 4; q++)
                sBf[bc8][4 * bg + q] = make_uint4(p[q].x, p[q].y, p[q + 4].x, p[q + 4].y);
            sV[r] = -0.5f * nrm;
            if (MODE == M_REF_W) sW[r] = g_Dref[cb + r];
        }
    }
    __syncthreads();

    const int ra0 = w * 16 + g;
    const int ra1 = ra0 + 8;
    const uint4 af0 = sAf[ra0][kq];
    const uint4 af1 = sAf[ra1][kq];
    const ull u0p = dup2(sU[ra0]);
    const ull u1p = dup2(sU[ra1]);

    float wr0 = 0.0f, wr1 = 0.0f;
    if (MODE == M_REF_W) { wr0 = sWa[ra0]; wr1 = sWa[ra1]; }

    // scalar accumulators (even/odd columns kept separate to shorten chains)
    float s1e0 = 0.0f, s1o0 = 0.0f, s1e1 = 0.0f, s1o1 = 0.0f;

#pragma unroll
    for (int cb8 = 0; cb8 < 16; cb8++) {
        const uint4 bf = sBf[cb8][lane];
        const int cl = cb8 * 8 + 2 * kq;
        const ull vvp = *reinterpret_cast<const ull*>(&sV[cl]);

        float d0, d1, d2, d3;
        unpackf2(add2p(u0p, vvp), d0, d1);
        unpackf2(add2p(u1p, vvp), d2, d3);
        mma16816(d0, d1, d2, d3, af0.x, af1.x, af0.z, af1.z, bf.x, bf.z);
        mma16816(d0, d1, d2, d3, af0.x, af1.x, af0.z, af1.z, bf.y, bf.w);
        mma16816(d0, d1, d2, d3, af0.y, af1.y, af0.w, af1.w, bf.x, bf.z);

        const float k00 = ex2_approx(d0);
        const float k01 = ex2_approx(d1);
        const float k10 = ex2_approx(d2);
        const float k11 = ex2_approx(d3);

        if (MODE == M_REF_SUM) {
            acc1(s1e0, k00); acc1(s1o0, k01);
            acc1(s1e1, k10); acc1(s1o1, k11);
        } else {
            const float2 ww = *reinterpret_cast<const float2*>(&sW[cl]);
            s1e0 = fmaf(k00, ww.x, s1e0); s1o0 = fmaf(k01, ww.y, s1o0);
            s1e1 = fmaf(k10, ww.x, s1e1); s1o1 = fmaf(k11, ww.y, s1o1);
        }

        if (offdiag) {
            float c0, c1;
            if (MODE == M_REF_SUM) {
                c0 = k00 + k10;
                c1 = k01 + k11;
            } else {
                c0 = fmaf(k00, wr0, k10 * wr1);
                c1 = fmaf(k01, wr0, k11 * wr1);
            }
#pragma unroll
            for (int off = 4; off <= 16; off <<= 1) {
                c0 += __shfl_xor_sync(0xffffffffu, c0, off);
                c1 += __shfl_xor_sync(0xffffffffu, c1, off);
            }
            if (g == 0) {
                sCol[w][cl] = c0;
                sCol[w][cl + 1] = c1;
            }
        }
    }

    {
        float s1_0 = s1e0 + s1o0;
        float s1_1 = s1e1 + s1o1;
#pragma unroll
        for (int off = 1; off <= 2; off <<= 1) {
            s1_0 += __shfl_xor_sync(0xffffffffu, s1_0, off);
            s1_1 += __shfl_xor_sync(0xffffffffu, s1_1, off);
        }
        if (kq == 0) {
            if (MODE == M_REF_SUM) {
                g_P1[(size_t)(rb + ra0) * NCT + bx] = s1_0;
                g_P1[(size_t)(rb + ra1) * NCT + bx] = s1_1;
            } else {
                g_P2[(size_t)(rb + ra0) * NCT + bx] = s1_0;
                g_P2[(size_t)(rb + ra1) * NCT + bx] = s1_1;
            }
        }
    }

    if (offdiag) {
        __syncthreads();
        if (tid < 128) {
            float s = 0.0f;
#pragma unroll
            for (int q = 0; q < 8; q++) s += sCol[q][tid];
            if (MODE == M_REF_SUM) g_P1[(size_t)(cb + tid) * NCT + by] = s;
            else                   g_P2[(size_t)(cb + tid) * NCT + by] = s;
        }
    }
}

// ===========================================================================
// RECT kernel (X passes): 256 rows x 128 cols; scalar FFMA accumulation.
// ===========================================================================
template <int MODE>
__global__ void __launch_bounds__(256, 3)
k_eval_rect(const float* __restrict__ A,
            const float* __restrict__ B,
            const float* __restrict__ lep,
            float* __restrict__ out) {
    __shared__ uint4 sAf[256][4];
    __shared__ uint4 sBf[16][32];
    __shared__ float sU[256], sV[128], sW[128], sBc[128];

    const int tid = threadIdx.x;
    const int w = tid >> 5;
    const int lane = tid & 31;
    const int g = lane >> 2;
    const int kq = lane & 3;
    const int rb = blockIdx.y * 256;
    const int cb = blockIdx.x * 128;

    const float eps = softplus_f(__ldg(lep));
    const float twoc2 = 2.0f * LOG2E / (4.0f * eps);
    const float sc = sqrtf(twoc2);

    {
        const float4* s4 = reinterpret_cast<const float4*>(A + (size_t)(rb + tid) * DIM);
        float v[16]; float nrm = 0.0f;
#pragma unroll
        for (int q = 0; q < 4; q++) {
            float4 t = s4[q];
            v[4 * q] = t.x * sc; v[4 * q + 1] = t.y * sc;
            v[4 * q + 2] = t.z * sc; v[4 * q + 3] = t.w * sc;
            nrm += v[4 * q] * v[4 * q] + v[4 * q + 1] * v[4 * q + 1] +
                   v[4 * q + 2] * v[4 * q + 2] + v[4 * q + 3] * v[4 * q + 3];
        }
        uint2 p[8];
#pragma unroll
        for (int kp = 0; kp < 8; kp++) p[kp] = pack_hilo(v[2 * kp], v[2 * kp + 1]);
#pragma unroll
        for (int q = 0; q < 4; q++)
            sAf[tid][q] = make_uint4(p[q].x, p[q].y, p[q + 4].x, p[q + 4].y);
        sU[tid] = -0.5f * nrm;
    }
    if (tid < 128) {
        const float4* s4 = reinterpret_cast<const float4*>(B + (size_t)(cb + tid) * DIM);
        float v[16]; float nrm = 0.0f;
#pragma unroll
        for (int q = 0; q < 4; q++) {
            float4 t = s4[q];
            v[4 * q] = t.x * sc; v[4 * q + 1] = t.y * sc;
            v[4 * q + 2] = t.z * sc; v[4 * q + 3] = t.w * sc;
            nrm += v[4 * q] * v[4 * q] + v[4 * q + 1] * v[4 * q + 1] +
                   v[4 * q + 2] * v[4 * q + 2] + v[4 * q + 3] * v[4 * q + 3];
        }
        uint2 p[8];
#pragma unroll
        for (int kp = 0; kp < 8; kp++) p[kp] = pack_hilo(v[2 * kp], v[2 * kp + 1]);
        const int bg = tid & 7;
        const int bc8 = tid >> 3;
#pragma unroll
        for (int q = 0; q < 4; q++)
            sBf[bc8][4 * bg + q] = make_uint4(p[q].x, p[q].y, p[q + 4].x, p[q + 4].y);
        sV[tid] = -0.5f * nrm;
        sW[tid] = g_Dref[cb + tid];
        if (MODE == M_X_WRITE) sBc[tid] = g_bcol[cb + tid];
    }
    __syncthreads();

    const int ra0 = w * 32 + g;
    const int ra1 = ra0 + 8;
    const int ra2 = ra0 + 16;
    const int ra3 = ra0 + 24;
    const uint4 af0 = sAf[ra0][kq];
    const uint4 af1 = sAf[ra1][kq];
    const uint4 af2 = sAf[ra2][kq];
    const uint4 af3 = sAf[ra3][kq];
    const ull u0p = dup2(sU[ra0]);
    const ull u1p = dup2(sU[ra1]);
    const ull u2p = dup2(sU[ra2]);
    const ull u3p = dup2(sU[ra3]);

    ull av0p = 0, av1p = 0, av2p = 0, av3p = 0;
    if (MODE == M_X_WRITE) {
        av0p = dup2(g_arow[rb + ra0]);
        av1p = dup2(g_arow[rb + ra1]);
        av2p = dup2(g_arow[rb + ra2]);
        av3p = dup2(g_arow[rb + ra3]);
    }

    // scalar accumulators for X_SUM
    float s1r[4] = {0.0f, 0.0f, 0.0f, 0.0f};
    float s1o[4] = {0.0f, 0.0f, 0.0f, 0.0f};
    float s2r[4] = {0.0f, 0.0f, 0.0f, 0.0f};
    float s2o[4] = {0.0f, 0.0f, 0.0f, 0.0f};

#pragma unroll
    for (int cb8 = 0; cb8 < 16; cb8++) {
        const uint4 bf = sBf[cb8][lane];
        const int cl = cb8 * 8 + 2 * kq;
        const ull vvp = *reinterpret_cast<const ull*>(&sV[cl]);

        float d0, d1, d2, d3, d4, d5, d6, d7;
        unpackf2(add2p(u0p, vvp), d0, d1);
        unpackf2(add2p(u1p, vvp), d2, d3);
        unpackf2(add2p(u2p, vvp), d4, d5);
        unpackf2(add2p(u3p, vvp), d6, d7);

        mma16816(d0, d1, d2, d3, af0.x, af1.x, af0.z, af1.z, bf.x, bf.z);
        mma16816(d0, d1, d2, d3, af0.x, af1.x, af0.z, af1.z, bf.y, bf.w);
        mma16816(d0, d1, d2, d3, af0.y, af1.y, af0.w, af1.w, bf.x, bf.z);
        mma16816(d4, d5, d6, d7, af2.x, af3.x, af2.z, af3.z, bf.x, bf.z);
        mma16816(d4, d5, d6, d7, af2.x, af3.x, af2.z, af3.z, bf.y, bf.w);
        mma16816(d4, d5, d6, d7, af2.y, af3.y, af2.w, af3.w, bf.x, bf.z);

        const float k0e = ex2_approx(d0), k0o = ex2_approx(d1);
        const float k1e = ex2_approx(d2), k1o = ex2_approx(d3);
        const float k2e = ex2_approx(d4), k2o = ex2_approx(d5);
        const float k3e = ex2_approx(d6), k3o = ex2_approx(d7);

        if (MODE == M_X_SUM) {
            const float2 ww = *reinterpret_cast<const float2*>(&sW[cl]);
            acc1(s1r[0], k0e); acc1(s1o[0], k0o);
            acc1(s1r[1], k1e); acc1(s1o[1], k1o);
            acc1(s1r[2], k2e); acc1(s1o[2], k2o);
            acc1(s1r[3], k3e); acc1(s1o[3], k3o);
            s2r[0] = fmaf(k0e, ww.x, s2r[0]); s2o[0] = fmaf(k0o, ww.y, s2o[0]);
            s2r[1] = fmaf(k1e, ww.x, s2r[1]); s2o[1] = fmaf(k1o, ww.y, s2o[1]);
            s2r[2] = fmaf(k2e, ww.x, s2r[2]); s2o[2] = fmaf(k2o, ww.y, s2o[2]);
            s2r[3] = fmaf(k3e, ww.x, s2r[3]); s2o[3] = fmaf(k3o, ww.y, s2o[3]);
        } else { // M_X_WRITE
            const ull bcp = *reinterpret_cast<const ull*>(&sBc[cl]);
            ull o0 = mul2p(mul2p(packf2(k0e, k0o), bcp), av0p);
            ull o1 = mul2p(mul2p(packf2(k1e, k1o), bcp), av1p);
            ull o2 = mul2p(mul2p(packf2(k2e, k2o), bcp), av2p);
            ull o3 = mul2p(mul2p(packf2(k3e, k3o), bcp), av3p);
            *reinterpret_cast<ull*>(out + (size_t)(rb + ra0) * NROWS + cb + cl) = o0;
            *reinterpret_cast<ull*>(out + (size_t)(rb + ra1) * NROWS + cb + cl) = o1;
            *reinterpret_cast<ull*>(out + (size_t)(rb + ra2) * NROWS + cb + cl) = o2;
            *reinterpret_cast<ull*>(out + (size_t)(rb + ra3) * NROWS + cb + cl) = o3;
        }
    }

    if (MODE == M_X_SUM) {
        float r1[4], r2[4];
#pragma unroll
        for (int i = 0; i < 4; i++) {
            r1[i] = s1r[i] + s1o[i];
            r2[i] = s2r[i] + s2o[i];
        }
#pragma unroll
        for (int off = 1; off <= 2; off <<= 1) {
#pragma unroll
            for (int i = 0; i < 4; i++) {
                r1[i] += __shfl_xor_sync(0xffffffffu, r1[i], off);
                r2[i] += __shfl_xor_sync(0xffffffffu, r2[i], off);
            }
        }
        if (kq == 0) {
            const int rows[4] = {ra0, ra1, ra2, ra3};
#pragma unroll
            for (int i = 0; i < 4; i++) {
                g_P1x[(size_t)(rb + rows[i]) * NCT + blockIdx.x] = r1[i];
                g_P2x[(size_t)(rb + rows[i]) * NCT + blockIdx.x] = r2[i];
            }
        }
    }
}

// ---------------------------------------------------------------------------
// warp-per-row reductions
// ---------------------------------------------------------------------------
__device__ __forceinline__ float warp_row_sum(const float* __restrict__ P,
                                              int row, int lane) {
    float2 p = reinterpret_cast<const float2*>(P + (size_t)row * NCT)[lane];
    float s = p.x + p.y;
#pragma unroll
    for (int off = 16; off >= 1; off >>= 1)
        s += __shfl_xor_sync(0xffffffffu, s, off);
    return s;
}

__global__ void k_dref(const float* __restrict__ ltp) {
    int row = blockIdx.x * 8 + (threadIdx.x >> 5);
    int lane = threadIdx.x & 31;
    float s = warp_row_sum(g_P1, row, lane);
    if (lane == 0) {
        float t = softplus_f(__ldg(ltp));
        g_Dref[row] = expf(-t * logf(s));
    }
}

__global__ void k_bfin() {
    int row = blockIdx.x * 8 + (threadIdx.x >> 5);
    int lane = threadIdx.x & 31;
    float T = warp_row_sum(g_P2, row, lane);
    if (lane == 0) {
        float dr = g_Dref[row];
        g_bcol[row] = dr * rsqrtf(dr * T);
    }
}

__global__ void k_arow(const float* __restrict__ ltp) {
    int row = blockIdx.x * 8 + (threadIdx.x >> 5);
    int lane = threadIdx.x & 31;
    float s1 = warp_row_sum(g_P1x, row, lane);
    float s2 = warp_row_sum(g_P2x, row, lane);
    if (lane == 0) {
        float t = softplus_f(__ldg(ltp));
        float dx = expf(-t * logf(s1));
        g_arow[row] = dx * rsqrtf(dx * s2);
    }
}

// ---------------------------------------------------------------------------
extern "C" void kernel_launch(void* const* d_in, const int* in_sizes, int n_in,
                              void* d_out, int out_size) {
    const float* X    = (const float*)d_in[0];
    const float* Xref = (const float*)d_in[1];
    const float* lep  = (const float*)d_in[2];
    const float* ltp  = (const float*)d_in[3];
    float* out = (float*)d_out;

    dim3 rgrid(NCT, NROWS / 256);
    const int rblocks = NROWS / 8;

    k_eval_sq<M_REF_SUM><<<NTRI, 256>>>(Xref, Xref, lep);             // 1
    k_dref<<<rblocks, 256>>>(ltp);                                    // 2
    k_eval_sq<M_REF_W><<<NTRI, 256>>>(Xref, Xref, lep);               // 3
    k_eval_rect<M_X_SUM><<<rgrid, 256>>>(X, Xref, lep, nullptr);      // 4  <- profiled
    k_bfin<<<rblocks, 256>>>();                                       // 5
    k_arow<<<rblocks, 256>>>(ltp);                                    // 6
    k_eval_rect<M_X_WRITE><<<rgrid, 256>>>(X, Xref, lep, out);        // 7
}

// round 14
// speedup vs baseline: 1.0130x; 1.0130x over previous
#include <cuda_runtime.h>
#include <cuda_bf16.h>
#include <cstdint>

#define NROWS 8192
#define DIM   16
#define NCT   64
#define NTRI  (NCT * (NCT + 1) / 2)   // 2080
#define LOG2E 1.4426950408889634f

typedef unsigned long long ull;

// ---- device scratch (static, no allocation) ----
__device__ float g_P1[NROWS * NCT];    // ref pass: sum K
__device__ float g_P2[NROWS * NCT];    // ref pass: sum K*Dref
__device__ float g_P1x[NROWS * NCT];   // x pass: sum K
__device__ float g_P2x[NROWS * NCT];   // x pass: sum K*Dref
__device__ float g_Dref[NROWS];
__device__ float g_bcol[NROWS];
__device__ float g_arow[NROWS];

__device__ __forceinline__ float ex2_approx(float x) {
    float r; asm("ex2.approx.f32 %0, %1;" : "=f"(r) : "f"(x)); return r;
}
__device__ __forceinline__ float softplus_f(float x) { return log1pf(expf(x)); }

// accumulate form: D += A*B (C == D)
__device__ __forceinline__ void mma16816(float& d0, float& d1, float& d2, float& d3,
                                         uint32_t a0, uint32_t a1, uint32_t a2, uint32_t a3,
                                         uint32_t b0, uint32_t b1) {
    asm volatile(
        "mma.sync.aligned.m16n8k16.row.col.f32.bf16.bf16.f32 "
        "{%0,%1,%2,%3}, {%4,%5,%6,%7}, {%8,%9}, {%0,%1,%2,%3};"
        : "+f"(d0), "+f"(d1), "+f"(d2), "+f"(d3)
        : "r"(a0), "r"(a1), "r"(a2), "r"(a3), "r"(b0), "r"(b1));
}

// zero-C form: D = A*B + (z,z,z,z); z is a persistent zero register
__device__ __forceinline__ void mma16816_z(float& d0, float& d1, float& d2, float& d3,
                                           uint32_t a0, uint32_t a1, uint32_t a2, uint32_t a3,
                                           uint32_t b0, uint32_t b1, float z) {
    asm volatile(
        "mma.sync.aligned.m16n8k16.row.col.f32.bf16.bf16.f32 "
        "{%0,%1,%2,%3}, {%4,%5,%6,%7}, {%8,%9}, {%10,%10,%10,%10};"
        : "=f"(d0), "=f"(d1), "=f"(d2), "=f"(d3)
        : "r"(a0), "r"(a1), "r"(a2), "r"(a3), "r"(b0), "r"(b1), "f"(z));
}

// ---- packed f32x2 helpers ----
__device__ __forceinline__ ull dup2(float x) {
    ull r; asm("mov.b64 %0, {%1, %1};" : "=l"(r) : "f"(x)); return r;
}
__device__ __forceinline__ ull packf2(float lo, float hi) {
    ull r; asm("mov.b64 %0, {%1, %2};" : "=l"(r) : "f"(lo), "f"(hi)); return r;
}
__device__ __forceinline__ void unpackf2(ull v, float& lo, float& hi) {
    asm("mov.b64 {%0, %1}, %2;" : "=f"(lo), "=f"(hi) : "l"(v));
}
__device__ __forceinline__ ull add2p(ull a, ull b) {
    ull d; asm("add.rn.f32x2 %0, %1, %2;" : "=l"(d) : "l"(a), "l"(b)); return d;
}
__device__ __forceinline__ ull mul2p(ull a, ull b) {
    ull d; asm("mul.rn.f32x2 %0, %1, %2;" : "=l"(d) : "l"(a), "l"(b)); return d;
}
__device__ __forceinline__ ull fma2p(ull a, ull b, ull c) {
    ull d; asm("fma.rn.f32x2 %0, %1, %2, %3;" : "=l"(d) : "l"(a), "l"(b), "l"(c)); return d;
}

// pack two floats into (hi bf16x2, lo bf16x2)
__device__ __forceinline__ uint2 pack_hilo(float x0, float x1) {
    uint32_t hw, lw;
    asm("cvt.rn.bf16x2.f32 %0, %2, %1;" : "=r"(hw) : "f"(x0), "f"(x1));
    float h0 = __bfloat162float(__ushort_as_bfloat16((unsigned short)(hw & 0xffffu)));
    float h1 = __bfloat162float(__ushort_as_bfloat16((unsigned short)(hw >> 16)));
    float l0 = x0 - h0;
    float l1 = x1 - h1;
    asm("cvt.rn.bf16x2.f32 %0, %2, %1;" : "=r"(lw) : "f"(l0), "f"(l1));
    uint2 r; r.x = hw; r.y = lw;
    return r;
}

#define M_REF_SUM 0
#define M_REF_W   1
#define M_X_SUM   2
#define M_X_WRITE 3

// ===========================================================================
// SQUARE symmetric kernel (ref passes) — exp-split epilogue.
// K = exp2(g) * Eu_i * Ev_j; row/col factors applied outside the hot loop.
// ===========================================================================
template <int MODE>
__global__ void __launch_bounds__(256, 4)
k_eval_sq(const float* __restrict__ A,
          const float* __restrict__ B,
          const float* __restrict__ lep) {
    __shared__ uint4 sAf[128][4];
    __shared__ uint4 sBf[16][32];
    __shared__ float sEuA[128];   // row-side Eu
    __shared__ float sEv[128];    // col-side Ev
    __shared__ float sCw[128];    // col coefficient for row sums (Ev or Ev*Dref)
    __shared__ float sWa[128];    // row-side Dref (REF_W)
    __shared__ float sCol[8][128];

    int bx, by;
    {
        int l = blockIdx.x;
        bx = (int)((sqrtf(8.0f * (float)l + 1.0f) - 1.0f) * 0.5f);
        while ((bx * (bx + 1)) / 2 > l) bx--;
        while (((bx + 1) * (bx + 2)) / 2 <= l) bx++;
        by = l - (bx * (bx + 1)) / 2;
    }
    const bool offdiag = (by != bx);

    const int tid = threadIdx.x;
    const int w = tid >> 5;
    const int lane = tid & 31;
    const int g = lane >> 2;
    const int kq = lane & 3;
    const int rb = by * 128;
    const int cb = bx * 128;

    const float eps = softplus_f(__ldg(lep));
    const float twoc2 = 2.0f * LOG2E / (4.0f * eps);
    const float sc = sqrtf(twoc2);
    const float zf = 0.0f;

    {
        const int r = tid & 127;
        const bool isA = (tid < 128);
        const float4* s4 = reinterpret_cast<const float4*>(
            (isA ? A + (size_t)(rb + r) * DIM : B + (size_t)(cb + r) * DIM));
        float v[16]; float nrm = 0.0f;
#pragma unroll
        for (int q = 0; q < 4; q++) {
            float4 t = s4[q];
            v[4 * q] = t.x * sc; v[4 * q + 1] = t.y * sc;
            v[4 * q + 2] = t.z * sc; v[4 * q + 3] = t.w * sc;
            nrm += v[4 * q] * v[4 * q] + v[4 * q + 1] * v[4 * q + 1] +
                   v[4 * q + 2] * v[4 * q + 2] + v[4 * q + 3] * v[4 * q + 3];
        }
        uint2 p[8];
#pragma unroll
        for (int kp = 0; kp < 8; kp++) p[kp] = pack_hilo(v[2 * kp], v[2 * kp + 1]);
        const float E = ex2_approx(-0.5f * nrm);
        if (isA) {
#pragma unroll
            for (int q = 0; q < 4; q++)
                sAf[r][q] = make_uint4(p[q].x, p[q].y, p[q + 4].x, p[q + 4].y);
            sEuA[r] = E;
            if (MODE == M_REF_W) sWa[r] = g_Dref[rb + r];
        } else {
            const int bg = r & 7;
            const int bc8 = r >> 3;
#pragma unroll
            for (int q = 0; q < 4; q++)
                sBf[bc8][4 * bg + q] = make_uint4(p[q].x, p[q].y, p[q + 4].x, p[q + 4].y);
            sEv[r] = E;
            sCw[r] = (MODE == M_REF_W) ? E * g_Dref[cb + r] : E;
        }
    }
    __syncthreads();

    const int ra0 = w * 16 + g;
    const int ra1 = ra0 + 8;
    const uint4 af0 = sAf[ra0][kq];
    const uint4 af1 = sAf[ra1][kq];
    const float eu0 = sEuA[ra0];
    const float eu1 = sEuA[ra1];

    // per-row coefficient for the transposed (column) sums
    ull cr0p = 0, cr1p = 0;
    if (offdiag) {
        const float c0 = (MODE == M_REF_W) ? eu0 * sWa[ra0] : eu0;
        const float c1 = (MODE == M_REF_W) ? eu1 * sWa[ra1] : eu1;
        cr0p = dup2(c0);
        cr1p = dup2(c1);
    }

    ull s1a = 0, s1b = 0;

#pragma unroll
    for (int cb8 = 0; cb8 < 16; cb8++) {
        const uint4 bf = sBf[cb8][lane];
        const int cl = cb8 * 8 + 2 * kq;
        const ull cwp = *reinterpret_cast<const ull*>(&sCw[cl]);

        float d0, d1, d2, d3;
        mma16816_z(d0, d1, d2, d3, af0.x, af1.x, af0.z, af1.z, bf.x, bf.z, zf);
        mma16816(d0, d1, d2, d3, af0.x, af1.x, af0.z, af1.z, bf.y, bf.w);
        mma16816(d0, d1, d2, d3, af0.y, af1.y, af0.w, af1.w, bf.x, bf.z);

        const ull egp0 = packf2(ex2_approx(d0), ex2_approx(d1));
        const ull egp1 = packf2(ex2_approx(d2), ex2_approx(d3));

        s1a = fma2p(egp0, cwp, s1a);
        s1b = fma2p(egp1, cwp, s1b);

        if (offdiag) {
            ull cp = fma2p(egp1, cr1p, mul2p(egp0, cr0p));
            float c0, c1;
            unpackf2(cp, c0, c1);
#pragma unroll
            for (int off = 4; off <= 16; off <<= 1) {
                c0 += __shfl_xor_sync(0xffffffffu, c0, off);
                c1 += __shfl_xor_sync(0xffffffffu, c1, off);
            }
            if (g == 0) {
                sCol[w][cl] = c0;
                sCol[w][cl + 1] = c1;
            }
        }
    }

    {
        float x, y;
        unpackf2(s1a, x, y); float s1_0 = (x + y) * eu0;
        unpackf2(s1b, x, y); float s1_1 = (x + y) * eu1;
#pragma unroll
        for (int off = 1; off <= 2; off <<= 1) {
            s1_0 += __shfl_xor_sync(0xffffffffu, s1_0, off);
            s1_1 += __shfl_xor_sync(0xffffffffu, s1_1, off);
        }
        if (kq == 0) {
            if (MODE == M_REF_SUM) {
                g_P1[(size_t)(rb + ra0) * NCT + bx] = s1_0;
                g_P1[(size_t)(rb + ra1) * NCT + bx] = s1_1;
            } else {
                g_P2[(size_t)(rb + ra0) * NCT + bx] = s1_0;
                g_P2[(size_t)(rb + ra1) * NCT + bx] = s1_1;
            }
        }
    }

    if (offdiag) {
        __syncthreads();
        if (tid < 128) {
            float s = 0.0f;
#pragma unroll
            for (int q = 0; q < 8; q++) s += sCol[q][tid];
            s *= sEv[tid];   // column factor applied once
            if (MODE == M_REF_SUM) g_P1[(size_t)(cb + tid) * NCT + by] = s;
            else                   g_P2[(size_t)(cb + tid) * NCT + by] = s;
        }
    }
}

// ===========================================================================
// RECT kernel (X passes): 256 rows x 128 cols; exp-split epilogue.
// ===========================================================================
template <int MODE>
__global__ void __launch_bounds__(256, 3)
k_eval_rect(const float* __restrict__ A,
            const float* __restrict__ B,
            const float* __restrict__ lep,
            float* __restrict__ out) {
    __shared__ uint4 sAf[256][4];
    __shared__ uint4 sBf[16][32];
    __shared__ float sEuA[256];
    __shared__ float sEv[128];    // Ev (X_SUM s1 coeff)
    __shared__ float sEw[128];    // Ev*Dref (X_SUM s2 coeff)
    __shared__ float sBc[128];    // Ev*bcol (X_WRITE coeff)

    const int tid = threadIdx.x;
    const int w = tid >> 5;
    const int lane = tid & 31;
    const int g = lane >> 2;
    const int kq = lane & 3;
    const int rb = blockIdx.y * 256;
    const int cb = blockIdx.x * 128;

    const float eps = softplus_f(__ldg(lep));
    const float twoc2 = 2.0f * LOG2E / (4.0f * eps);
    const float sc = sqrtf(twoc2);
    const float zf = 0.0f;

    {
        const float4* s4 = reinterpret_cast<const float4*>(A + (size_t)(rb + tid) * DIM);
        float v[16]; float nrm = 0.0f;
#pragma unroll
        for (int q = 0; q < 4; q++) {
            float4 t = s4[q];
            v[4 * q] = t.x * sc; v[4 * q + 1] = t.y * sc;
            v[4 * q + 2] = t.z * sc; v[4 * q + 3] = t.w * sc;
            nrm += v[4 * q] * v[4 * q] + v[4 * q + 1] * v[4 * q + 1] +
                   v[4 * q + 2] * v[4 * q + 2] + v[4 * q + 3] * v[4 * q + 3];
        }
        uint2 p[8];
#pragma unroll
        for (int kp = 0; kp < 8; kp++) p[kp] = pack_hilo(v[2 * kp], v[2 * kp + 1]);
#pragma unroll
        for (int q = 0; q < 4; q++)
            sAf[tid][q] = make_uint4(p[q].x, p[q].y, p[q + 4].x, p[q + 4].y);
        sEuA[tid] = ex2_approx(-0.5f * nrm);
    }
    if (tid < 128) {
        const float4* s4 = reinterpret_cast<const float4*>(B + (size_t)(cb + tid) * DIM);
        float v[16]; float nrm = 0.0f;
#pragma unroll
        for (int q = 0; q < 4; q++) {
            float4 t = s4[q];
            v[4 * q] = t.x * sc; v[4 * q + 1] = t.y * sc;
            v[4 * q + 2] = t.z * sc; v[4 * q + 3] = t.w * sc;
            nrm += v[4 * q] * v[4 * q] + v[4 * q + 1] * v[4 * q + 1] +
                   v[4 * q + 2] * v[4 * q + 2] + v[4 * q + 3] * v[4 * q + 3];
        }
        uint2 p[8];
#pragma unroll
        for (int kp = 0; kp < 8; kp++) p[kp] = pack_hilo(v[2 * kp], v[2 * kp + 1]);
        const int bg = tid & 7;
        const int bc8 = tid >> 3;
#pragma unroll
        for (int q = 0; q < 4; q++)
            sBf[bc8][4 * bg + q] = make_uint4(p[q].x, p[q].y, p[q + 4].x, p[q + 4].y);
        const float E = ex2_approx(-0.5f * nrm);
        sEv[tid] = E;
        if (MODE == M_X_SUM)   sEw[tid] = E * g_Dref[cb + tid];
        if (MODE == M_X_WRITE) sBc[tid] = E * g_bcol[cb + tid];
    }
    __syncthreads();

    const int ra0 = w * 32 + g;
    const int ra1 = ra0 + 8;
    const int ra2 = ra0 + 16;
    const int ra3 = ra0 + 24;
    const uint4 af0 = sAf[ra0][kq];
    const uint4 af1 = sAf[ra1][kq];
    const uint4 af2 = sAf[ra2][kq];
    const uint4 af3 = sAf[ra3][kq];
    const float eu0 = sEuA[ra0];
    const float eu1 = sEuA[ra1];
    const float eu2 = sEuA[ra2];
    const float eu3 = sEuA[ra3];

    ull rc0p = 0, rc1p = 0, rc2p = 0, rc3p = 0;
    if (MODE == M_X_WRITE) {
        rc0p = dup2(eu0 * g_arow[rb + ra0]);
        rc1p = dup2(eu1 * g_arow[rb + ra1]);
        rc2p = dup2(eu2 * g_arow[rb + ra2]);
        rc3p = dup2(eu3 * g_arow[rb + ra3]);
    }

    ull s1_0 = 0, s1_1 = 0, s1_2 = 0, s1_3 = 0;
    ull s2_0 = 0, s2_1 = 0, s2_2 = 0, s2_3 = 0;

#pragma unroll
    for (int cb8 = 0; cb8 < 16; cb8++) {
        const uint4 bf = sBf[cb8][lane];
        const int cl = cb8 * 8 + 2 * kq;

        float d0, d1, d2, d3, d4, d5, d6, d7;
        mma16816_z(d0, d1, d2, d3, af0.x, af1.x, af0.z, af1.z, bf.x, bf.z, zf);
        mma16816(d0, d1, d2, d3, af0.x, af1.x, af0.z, af1.z, bf.y, bf.w);
        mma16816(d0, d1, d2, d3, af0.y, af1.y, af0.w, af1.w, bf.x, bf.z);
        mma16816_z(d4, d5, d6, d7, af2.x, af3.x, af2.z, af3.z, bf.x, bf.z, zf);
        mma16816(d4, d5, d6, d7, af2.x, af3.x, af2.z, af3.z, bf.y, bf.w);
        mma16816(d4, d5, d6, d7, af2.y, af3.y, af2.w, af3.w, bf.x, bf.z);

        const ull egp0 = packf2(ex2_approx(d0), ex2_approx(d1));
        const ull egp1 = packf2(ex2_approx(d2), ex2_approx(d3));
        const ull egp2 = packf2(ex2_approx(d4), ex2_approx(d5));
        const ull egp3 = packf2(ex2_approx(d6), ex2_approx(d7));

        if (MODE == M_X_SUM) {
            const ull evp = *reinterpret_cast<const ull*>(&sEv[cl]);
            const ull ewp = *reinterpret_cast<const ull*>(&sEw[cl]);
            s1_0 = fma2p(egp0, evp, s1_0);
            s1_1 = fma2p(egp1, evp, s1_1);
            s1_2 = fma2p(egp2, evp, s1_2);
            s1_3 = fma2p(egp3, evp, s1_3);
            s2_0 = fma2p(egp0, ewp, s2_0);
            s2_1 = fma2p(egp1, ewp, s2_1);
            s2_2 = fma2p(egp2, ewp, s2_2);
            s2_3 = fma2p(egp3, ewp, s2_3);
        } else { // M_X_WRITE
            const ull bcp = *reinterpret_cast<const ull*>(&sBc[cl]);
            ull o0 = mul2p(mul2p(egp0, bcp), rc0p);
            ull o1 = mul2p(mul2p(egp1, bcp), rc1p);
            ull o2 = mul2p(mul2p(egp2, bcp), rc2p);
            ull o3 = mul2p(mul2p(egp3, bcp), rc3p);
            *reinterpret_cast<ull*>(out + (size_t)(rb + ra0) * NROWS + cb + cl) = o0;
            *reinterpret_cast<ull*>(out + (size_t)(rb + ra1) * NROWS + cb + cl) = o1;
            *reinterpret_cast<ull*>(out + (size_t)(rb + ra2) * NROWS + cb + cl) = o2;
            *reinterpret_cast<ull*>(out + (size_t)(rb + ra3) * NROWS + cb + cl) = o3;
        }
    }

    if (MODE == M_X_SUM) {
        const float eus[4] = {eu0, eu1, eu2, eu3};
        const ull s1p[4] = {s1_0, s1_1, s1_2, s1_3};
        const ull s2p[4] = {s2_0, s2_1, s2_2, s2_3};
        float r1[4], r2[4];
#pragma unroll
        for (int i = 0; i < 4; i++) {
            float x, y;
            unpackf2(s1p[i], x, y); r1[i] = (x + y) * eus[i];
            unpackf2(s2p[i], x, y); r2[i] = (x + y) * eus[i];
        }
#pragma unroll
        for (int off = 1; off <= 2; off <<= 1) {
#pragma unroll
            for (int i = 0; i < 4; i++) {
                r1[i] += __shfl_xor_sync(0xffffffffu, r1[i], off);
                r2[i] += __shfl_xor_sync(0xffffffffu, r2[i], off);
            }
        }
        if (kq == 0) {
            const int rows[4] = {ra0, ra1, ra2, ra3};
#pragma unroll
            for (int i = 0; i < 4; i++) {
                g_P1x[(size_t)(rb + rows[i]) * NCT + blockIdx.x] = r1[i];
                g_P2x[(size_t)(rb + rows[i]) * NCT + blockIdx.x] = r2[i];
            }
        }
    }
}

// ---------------------------------------------------------------------------
// warp-per-row reductions
// ---------------------------------------------------------------------------
__device__ __forceinline__ float warp_row_sum(const float* __restrict__ P,
                                              int row, int lane) {
    float2 p = reinterpret_cast<const float2*>(P + (size_t)row * NCT)[lane];
    float s = p.x + p.y;
#pragma unroll
    for (int off = 16; off >= 1; off >>= 1)
        s += __shfl_xor_sync(0xffffffffu, s, off);
    return s;
}

__global__ void k_dref(const float* __restrict__ ltp) {
    int row = blockIdx.x * 8 + (threadIdx.x >> 5);
    int lane = threadIdx.x & 31;
    float s = warp_row_sum(g_P1, row, lane);
    if (lane == 0) {
        float t = softplus_f(__ldg(ltp));
        g_Dref[row] = expf(-t * logf(s));
    }
}

__global__ void k_bfin() {
    int row = blockIdx.x * 8 + (threadIdx.x >> 5);
    int lane = threadIdx.x & 31;
    float T = warp_row_sum(g_P2, row, lane);
    if (lane == 0) {
        float dr = g_Dref[row];
        g_bcol[row] = dr * rsqrtf(dr * T);
    }
}

__global__ void k_arow(const float* __restrict__ ltp) {
    int row = blockIdx.x * 8 + (threadIdx.x >> 5);
    int lane = threadIdx.x & 31;
    float s1 = warp_row_sum(g_P1x, row, lane);
    float s2 = warp_row_sum(g_P2x, row, lane);
    if (lane == 0) {
        float t = softplus_f(__ldg(ltp));
        float dx = expf(-t * logf(s1));
        g_arow[row] = dx * rsqrtf(dx * s2);
    }
}

// ---------------------------------------------------------------------------
extern "C" void kernel_launch(void* const* d_in, const int* in_sizes, int n_in,
                              void* d_out, int out_size) {
    const float* X    = (const float*)d_in[0];
    const float* Xref = (const float*)d_in[1];
    const float* lep  = (const float*)d_in[2];
    const float* ltp  = (const float*)d_in[3];
    float* out = (float*)d_out;

    dim3 rgrid(NCT, NROWS / 256);
    const int rblocks = NROWS / 8;

    k_eval_sq<M_REF_SUM><<<NTRI, 256>>>(Xref, Xref, lep);             // 1
    k_dref<<<rblocks, 256>>>(ltp);                                    // 2
    k_eval_sq<M_REF_W><<<NTRI, 256>>>(Xref, Xref, lep);               // 3
    k_eval_rect<M_X_SUM><<<rgrid, 256>>>(X, Xref, lep, nullptr);      // 4  <- profiled
    k_bfin<<<rblocks, 256>>>();                                       // 5
    k_arow<<<rblocks, 256>>>(ltp);                                    // 6
    k_eval_rect<M_X_WRITE><<<rgrid, 256>>>(X, Xref, lep, out);        // 7
}

// round 15
// speedup vs baseline: 1.0280x; 1.0147x over previous
#include <cuda_runtime.h>
#include <cuda_bf16.h>
#include <cstdint>

#define NROWS 8192
#define DIM   16
#define NCT   64
#define NTRI  (NCT * (NCT + 1) / 2)   // 2080
#define LOG2E 1.4426950408889634f

typedef unsigned long long ull;

// ---- device scratch (static, no allocation) ----
__device__ float g_P1[NROWS * NCT];    // ref pass: sum K
__device__ float g_P2[NROWS * NCT];    // ref pass: sum K*Dref
__device__ float g_P1x[NROWS * NCT];   // x pass: sum K
__device__ float g_P2x[NROWS * NCT];   // x pass: sum K*Dref
__device__ float g_Dref[NROWS];
__device__ float g_bcol[NROWS];
__device__ float g_arow[NROWS];

__device__ __forceinline__ float ex2_approx(float x) {
    float r; asm("ex2.approx.f32 %0, %1;" : "=f"(r) : "f"(x)); return r;
}
__device__ __forceinline__ float softplus_f(float x) { return log1pf(expf(x)); }

// accumulate form: D += A*B (C == D)
__device__ __forceinline__ void mma16816(float& d0, float& d1, float& d2, float& d3,
                                         uint32_t a0, uint32_t a1, uint32_t a2, uint32_t a3,
                                         uint32_t b0, uint32_t b1) {
    asm volatile(
        "mma.sync.aligned.m16n8k16.row.col.f32.bf16.bf16.f32 "
        "{%0,%1,%2,%3}, {%4,%5,%6,%7}, {%8,%9}, {%0,%1,%2,%3};"
        : "+f"(d0), "+f"(d1), "+f"(d2), "+f"(d3)
        : "r"(a0), "r"(a1), "r"(a2), "r"(a3), "r"(b0), "r"(b1));
}

// zero-C form: D = A*B + (z,z,z,z)
__device__ __forceinline__ void mma16816_z(float& d0, float& d1, float& d2, float& d3,
                                           uint32_t a0, uint32_t a1, uint32_t a2, uint32_t a3,
                                           uint32_t b0, uint32_t b1, float z) {
    asm volatile(
        "mma.sync.aligned.m16n8k16.row.col.f32.bf16.bf16.f32 "
        "{%0,%1,%2,%3}, {%4,%5,%6,%7}, {%8,%9}, {%10,%10,%10,%10};"
        : "=f"(d0), "=f"(d1), "=f"(d2), "=f"(d3)
        : "r"(a0), "r"(a1), "r"(a2), "r"(a3), "r"(b0), "r"(b1), "f"(z));
}

// ---- packed f32x2 helpers ----
__device__ __forceinline__ ull dup2(float x) {
    ull r; asm("mov.b64 %0, {%1, %1};" : "=l"(r) : "f"(x)); return r;
}
__device__ __forceinline__ ull packf2(float lo, float hi) {
    ull r; asm("mov.b64 %0, {%1, %2};" : "=l"(r) : "f"(lo), "f"(hi)); return r;
}
__device__ __forceinline__ void unpackf2(ull v, float& lo, float& hi) {
    asm("mov.b64 {%0, %1}, %2;" : "=f"(lo), "=f"(hi) : "l"(v));
}
__device__ __forceinline__ ull mul2p(ull a, ull b) {
    ull d; asm("mul.rn.f32x2 %0, %1, %2;" : "=l"(d) : "l"(a), "l"(b)); return d;
}
__device__ __forceinline__ ull fma2p(ull a, ull b, ull c) {
    ull d; asm("fma.rn.f32x2 %0, %1, %2, %3;" : "=l"(d) : "l"(a), "l"(b), "l"(c)); return d;
}

// pack two floats into (hi bf16x2, lo bf16x2)
__device__ __forceinline__ uint2 pack_hilo(float x0, float x1) {
    uint32_t hw, lw;
    asm("cvt.rn.bf16x2.f32 %0, %2, %1;" : "=r"(hw) : "f"(x0), "f"(x1));
    float h0 = __bfloat162float(__ushort_as_bfloat16((unsigned short)(hw & 0xffffu)));
    float h1 = __bfloat162float(__ushort_as_bfloat16((unsigned short)(hw >> 16)));
    float l0 = x0 - h0;
    float l1 = x1 - h1;
    asm("cvt.rn.bf16x2.f32 %0, %2, %1;" : "=r"(lw) : "f"(l0), "f"(l1));
    uint2 r; r.x = hw; r.y = lw;
    return r;
}

#define M_REF_SUM 0
#define M_REF_W   1
#define M_X_SUM   2
#define M_X_WRITE 3

// ===========================================================================
// SQUARE symmetric kernel (ref passes) — exp-split epilogue (unchanged R14)
// ===========================================================================
template <int MODE>
__global__ void __launch_bounds__(256, 4)
k_eval_sq(const float* __restrict__ A,
          const float* __restrict__ B,
          const float* __restrict__ lep) {
    __shared__ uint4 sAf[128][4];
    __shared__ uint4 sBf[16][32];
    __shared__ float sEuA[128];
    __shared__ float sEv[128];
    __shared__ float sCw[128];
    __shared__ float sWa[128];
    __shared__ float sCol[8][128];

    int bx, by;
    {
        int l = blockIdx.x;
        bx = (int)((sqrtf(8.0f * (float)l + 1.0f) - 1.0f) * 0.5f);
        while ((bx * (bx + 1)) / 2 > l) bx--;
        while (((bx + 1) * (bx + 2)) / 2 <= l) bx++;
        by = l - (bx * (bx + 1)) / 2;
    }
    const bool offdiag = (by != bx);

    const int tid = threadIdx.x;
    const int w = tid >> 5;
    const int lane = tid & 31;
    const int g = lane >> 2;
    const int kq = lane & 3;
    const int rb = by * 128;
    const int cb = bx * 128;

    const float eps = softplus_f(__ldg(lep));
    const float twoc2 = 2.0f * LOG2E / (4.0f * eps);
    const float sc = sqrtf(twoc2);
    const float zf = 0.0f;

    {
        const int r = tid & 127;
        const bool isA = (tid < 128);
        const float4* s4 = reinterpret_cast<const float4*>(
            (isA ? A + (size_t)(rb + r) * DIM : B + (size_t)(cb + r) * DIM));
        float v[16]; float nrm = 0.0f;
#pragma unroll
        for (int q = 0; q < 4; q++) {
            float4 t = s4[q];
            v[4 * q] = t.x * sc; v[4 * q + 1] = t.y * sc;
            v[4 * q + 2] = t.z * sc; v[4 * q + 3] = t.w * sc;
            nrm += v[4 * q] * v[4 * q] + v[4 * q + 1] * v[4 * q + 1] +
                   v[4 * q + 2] * v[4 * q + 2] + v[4 * q + 3] * v[4 * q + 3];
        }
        uint2 p[8];
#pragma unroll
        for (int kp = 0; kp < 8; kp++) p[kp] = pack_hilo(v[2 * kp], v[2 * kp + 1]);
        const float E = ex2_approx(-0.5f * nrm);
        if (isA) {
#pragma unroll
            for (int q = 0; q < 4; q++)
                sAf[r][q] = make_uint4(p[q].x, p[q].y, p[q + 4].x, p[q + 4].y);
            sEuA[r] = E;
            if (MODE == M_REF_W) sWa[r] = g_Dref[rb + r];
        } else {
            const int bg = r & 7;
            const int bc8 = r >> 3;
#pragma unroll
            for (int q = 0; q < 4; q++)
                sBf[bc8][4 * bg + q] = make_uint4(p[q].x, p[q].y, p[q + 4].x, p[q + 4].y);
            sEv[r] = E;
            sCw[r] = (MODE == M_REF_W) ? E * g_Dref[cb + r] : E;
        }
    }
    __syncthreads();

    const int ra0 = w * 16 + g;
    const int ra1 = ra0 + 8;
    const uint4 af0 = sAf[ra0][kq];
    const uint4 af1 = sAf[ra1][kq];
    const float eu0 = sEuA[ra0];
    const float eu1 = sEuA[ra1];

    ull cr0p = 0, cr1p = 0;
    if (offdiag) {
        const float c0 = (MODE == M_REF_W) ? eu0 * sWa[ra0] : eu0;
        const float c1 = (MODE == M_REF_W) ? eu1 * sWa[ra1] : eu1;
        cr0p = dup2(c0);
        cr1p = dup2(c1);
    }

    ull s1a = 0, s1b = 0;

#pragma unroll
    for (int cb8 = 0; cb8 < 16; cb8++) {
        const uint4 bf = sBf[cb8][lane];
        const int cl = cb8 * 8 + 2 * kq;
        const ull cwp = *reinterpret_cast<const ull*>(&sCw[cl]);

        float d0, d1, d2, d3;
        mma16816_z(d0, d1, d2, d3, af0.x, af1.x, af0.z, af1.z, bf.x, bf.z, zf);
        mma16816(d0, d1, d2, d3, af0.x, af1.x, af0.z, af1.z, bf.y, bf.w);
        mma16816(d0, d1, d2, d3, af0.y, af1.y, af0.w, af1.w, bf.x, bf.z);

        const ull egp0 = packf2(ex2_approx(d0), ex2_approx(d1));
        const ull egp1 = packf2(ex2_approx(d2), ex2_approx(d3));

        s1a = fma2p(egp0, cwp, s1a);
        s1b = fma2p(egp1, cwp, s1b);

        if (offdiag) {
            ull cp = fma2p(egp1, cr1p, mul2p(egp0, cr0p));
            float c0, c1;
            unpackf2(cp, c0, c1);
#pragma unroll
            for (int off = 4; off <= 16; off <<= 1) {
                c0 += __shfl_xor_sync(0xffffffffu, c0, off);
                c1 += __shfl_xor_sync(0xffffffffu, c1, off);
            }
            if (g == 0) {
                sCol[w][cl] = c0;
                sCol[w][cl + 1] = c1;
            }
        }
    }

    {
        float x, y;
        unpackf2(s1a, x, y); float s1_0 = (x + y) * eu0;
        unpackf2(s1b, x, y); float s1_1 = (x + y) * eu1;
#pragma unroll
        for (int off = 1; off <= 2; off <<= 1) {
            s1_0 += __shfl_xor_sync(0xffffffffu, s1_0, off);
            s1_1 += __shfl_xor_sync(0xffffffffu, s1_1, off);
        }
        if (kq == 0) {
            if (MODE == M_REF_SUM) {
                g_P1[(size_t)(rb + ra0) * NCT + bx] = s1_0;
                g_P1[(size_t)(rb + ra1) * NCT + bx] = s1_1;
            } else {
                g_P2[(size_t)(rb + ra0) * NCT + bx] = s1_0;
                g_P2[(size_t)(rb + ra1) * NCT + bx] = s1_1;
            }
        }
    }

    if (offdiag) {
        __syncthreads();
        if (tid < 128) {
            float s = 0.0f;
#pragma unroll
            for (int q = 0; q < 8; q++) s += sCol[q][tid];
            s *= sEv[tid];
            if (MODE == M_REF_SUM) g_P1[(size_t)(cb + tid) * NCT + by] = s;
            else                   g_P2[(size_t)(cb + tid) * NCT + by] = s;
        }
    }
}

// ===========================================================================
// RECT kernel (X passes): 256x128; scalar chained accumulation, occ 4/SM.
// ===========================================================================
template <int MODE>
__global__ void __launch_bounds__(256, 4)
k_eval_rect(const float* __restrict__ A,
            const float* __restrict__ B,
            const float* __restrict__ lep,
            float* __restrict__ out) {
    __shared__ uint4 sAf[256][4];
    __shared__ uint4 sBf[16][32];
    __shared__ float sEuA[256];
    __shared__ float sEv[128];    // Ev
    __shared__ float sEw[128];    // Ev*Dref
    __shared__ float sBc[128];    // Ev*bcol

    const int tid = threadIdx.x;
    const int w = tid >> 5;
    const int lane = tid & 31;
    const int g = lane >> 2;
    const int kq = lane & 3;
    const int rb = blockIdx.y * 256;
    const int cb = blockIdx.x * 128;

    const float eps = softplus_f(__ldg(lep));
    const float twoc2 = 2.0f * LOG2E / (4.0f * eps);
    const float sc = sqrtf(twoc2);
    const float zf = 0.0f;

    {
        const float4* s4 = reinterpret_cast<const float4*>(A + (size_t)(rb + tid) * DIM);
        float v[16]; float nrm = 0.0f;
#pragma unroll
        for (int q = 0; q < 4; q++) {
            float4 t = s4[q];
            v[4 * q] = t.x * sc; v[4 * q + 1] = t.y * sc;
            v[4 * q + 2] = t.z * sc; v[4 * q + 3] = t.w * sc;
            nrm += v[4 * q] * v[4 * q] + v[4 * q + 1] * v[4 * q + 1] +
                   v[4 * q + 2] * v[4 * q + 2] + v[4 * q + 3] * v[4 * q + 3];
        }
        uint2 p[8];
#pragma unroll
        for (int kp = 0; kp < 8; kp++) p[kp] = pack_hilo(v[2 * kp], v[2 * kp + 1]);
#pragma unroll
        for (int q = 0; q < 4; q++)
            sAf[tid][q] = make_uint4(p[q].x, p[q].y, p[q + 4].x, p[q + 4].y);
        sEuA[tid] = ex2_approx(-0.5f * nrm);
    }
    if (tid < 128) {
        const float4* s4 = reinterpret_cast<const float4*>(B + (size_t)(cb + tid) * DIM);
        float v[16]; float nrm = 0.0f;
#pragma unroll
        for (int q = 0; q < 4; q++) {
            float4 t = s4[q];
            v[4 * q] = t.x * sc; v[4 * q + 1] = t.y * sc;
            v[4 * q + 2] = t.z * sc; v[4 * q + 3] = t.w * sc;
            nrm += v[4 * q] * v[4 * q] + v[4 * q + 1] * v[4 * q + 1] +
                   v[4 * q + 2] * v[4 * q + 2] + v[4 * q + 3] * v[4 * q + 3];
        }
        uint2 p[8];
#pragma unroll
        for (int kp = 0; kp < 8; kp++) p[kp] = pack_hilo(v[2 * kp], v[2 * kp + 1]);
        const int bg = tid & 7;
        const int bc8 = tid >> 3;
#pragma unroll
        for (int q = 0; q < 4; q++)
            sBf[bc8][4 * bg + q] = make_uint4(p[q].x, p[q].y, p[q + 4].x, p[q + 4].y);
        const float E = ex2_approx(-0.5f * nrm);
        sEv[tid] = E;
        if (MODE == M_X_SUM)   sEw[tid] = E * g_Dref[cb + tid];
        if (MODE == M_X_WRITE) sBc[tid] = E * g_bcol[cb + tid];
    }
    __syncthreads();

    const int ra0 = w * 32 + g;
    const int ra1 = ra0 + 8;
    const int ra2 = ra0 + 16;
    const int ra3 = ra0 + 24;
    const uint4 af0 = sAf[ra0][kq];
    const uint4 af1 = sAf[ra1][kq];
    const uint4 af2 = sAf[ra2][kq];
    const uint4 af3 = sAf[ra3][kq];
    const float eu0 = sEuA[ra0];
    const float eu1 = sEuA[ra1];
    const float eu2 = sEuA[ra2];
    const float eu3 = sEuA[ra3];

    ull rc0p = 0, rc1p = 0, rc2p = 0, rc3p = 0;
    if (MODE == M_X_WRITE) {
        rc0p = dup2(eu0 * g_arow[rb + ra0]);
        rc1p = dup2(eu1 * g_arow[rb + ra1]);
        rc2p = dup2(eu2 * g_arow[rb + ra2]);
        rc3p = dup2(eu3 * g_arow[rb + ra3]);
    }

    // scalar accumulators (X_SUM): 8 floats instead of 8 reg-pairs
    float s1[4] = {0.0f, 0.0f, 0.0f, 0.0f};
    float s2[4] = {0.0f, 0.0f, 0.0f, 0.0f};

#pragma unroll
    for (int cb8 = 0; cb8 < 16; cb8++) {
        const uint4 bf = sBf[cb8][lane];
        const int cl = cb8 * 8 + 2 * kq;

        float d0, d1, d2, d3, d4, d5, d6, d7;
        mma16816_z(d0, d1, d2, d3, af0.x, af1.x, af0.z, af1.z, bf.x, bf.z, zf);
        mma16816(d0, d1, d2, d3, af0.x, af1.x, af0.z, af1.z, bf.y, bf.w);
        mma16816(d0, d1, d2, d3, af0.y, af1.y, af0.w, af1.w, bf.x, bf.z);
        mma16816_z(d4, d5, d6, d7, af2.x, af3.x, af2.z, af3.z, bf.x, bf.z, zf);
        mma16816(d4, d5, d6, d7, af2.x, af3.x, af2.z, af3.z, bf.y, bf.w);
        mma16816(d4, d5, d6, d7, af2.y, af3.y, af2.w, af3.w, bf.x, bf.z);

        const float k0e = ex2_approx(d0), k0o = ex2_approx(d1);
        const float k1e = ex2_approx(d2), k1o = ex2_approx(d3);
        const float k2e = ex2_approx(d4), k2o = ex2_approx(d5);
        const float k3e = ex2_approx(d6), k3o = ex2_approx(d7);

        if (MODE == M_X_SUM) {
            const float2 ev = *reinterpret_cast<const float2*>(&sEv[cl]);
            const float2 ew = *reinterpret_cast<const float2*>(&sEw[cl]);
            s1[0] = fmaf(k0o, ev.y, fmaf(k0e, ev.x, s1[0]));
            s1[1] = fmaf(k1o, ev.y, fmaf(k1e, ev.x, s1[1]));
            s1[2] = fmaf(k2o, ev.y, fmaf(k2e, ev.x, s1[2]));
            s1[3] = fmaf(k3o, ev.y, fmaf(k3e, ev.x, s1[3]));
            s2[0] = fmaf(k0o, ew.y, fmaf(k0e, ew.x, s2[0]));
            s2[1] = fmaf(k1o, ew.y, fmaf(k1e, ew.x, s2[1]));
            s2[2] = fmaf(k2o, ew.y, fmaf(k2e, ew.x, s2[2]));
            s2[3] = fmaf(k3o, ew.y, fmaf(k3e, ew.x, s2[3]));
        } else { // M_X_WRITE
            const ull bcp = *reinterpret_cast<const ull*>(&sBc[cl]);
            ull o0 = mul2p(mul2p(packf2(k0e, k0o), bcp), rc0p);
            ull o1 = mul2p(mul2p(packf2(k1e, k1o), bcp), rc1p);
            ull o2 = mul2p(mul2p(packf2(k2e, k2o), bcp), rc2p);
            ull o3 = mul2p(mul2p(packf2(k3e, k3o), bcp), rc3p);
            *reinterpret_cast<ull*>(out + (size_t)(rb + ra0) * NROWS + cb + cl) = o0;
            *reinterpret_cast<ull*>(out + (size_t)(rb + ra1) * NROWS + cb + cl) = o1;
            *reinterpret_cast<ull*>(out + (size_t)(rb + ra2) * NROWS + cb + cl) = o2;
            *reinterpret_cast<ull*>(out + (size_t)(rb + ra3) * NROWS + cb + cl) = o3;
        }
    }

    if (MODE == M_X_SUM) {
        const float eus[4] = {eu0, eu1, eu2, eu3};
        float r1[4], r2[4];
#pragma unroll
        for (int i = 0; i < 4; i++) {
            r1[i] = s1[i] * eus[i];
            r2[i] = s2[i] * eus[i];
        }
#pragma unroll
        for (int off = 1; off <= 2; off <<= 1) {
#pragma unroll
            for (int i = 0; i < 4; i++) {
                r1[i] += __shfl_xor_sync(0xffffffffu, r1[i], off);
                r2[i] += __shfl_xor_sync(0xffffffffu, r2[i], off);
            }
        }
        if (kq == 0) {
            const int rows[4] = {ra0, ra1, ra2, ra3};
#pragma unroll
            for (int i = 0; i < 4; i++) {
                g_P1x[(size_t)(rb + rows[i]) * NCT + blockIdx.x] = r1[i];
                g_P2x[(size_t)(rb + rows[i]) * NCT + blockIdx.x] = r2[i];
            }
        }
    }
}

// ---------------------------------------------------------------------------
// warp-per-row reductions
// ---------------------------------------------------------------------------
__device__ __forceinline__ float warp_row_sum(const float* __restrict__ P,
                                              int row, int lane) {
    float2 p = reinterpret_cast<const float2*>(P + (size_t)row * NCT)[lane];
    float s = p.x + p.y;
#pragma unroll
    for (int off = 16; off >= 1; off >>= 1)
        s += __shfl_xor_sync(0xffffffffu, s, off);
    return s;
}

__global__ void k_dref(const float* __restrict__ ltp) {
    int row = blockIdx.x * 8 + (threadIdx.x >> 5);
    int lane = threadIdx.x & 31;
    float s = warp_row_sum(g_P1, row, lane);
    if (lane == 0) {
        float t = softplus_f(__ldg(ltp));
        g_Dref[row] = expf(-t * logf(s));
    }
}

__global__ void k_bfin() {
    int row = blockIdx.x * 8 + (threadIdx.x >> 5);
    int lane = threadIdx.x & 31;
    float T = warp_row_sum(g_P2, row, lane);
    if (lane == 0) {
        float dr = g_Dref[row];
        g_bcol[row] = dr * rsqrtf(dr * T);
    }
}

__global__ void k_arow(const float* __restrict__ ltp) {
    int row = blockIdx.x * 8 + (threadIdx.x >> 5);
    int lane = threadIdx.x & 31;
    float s1 = warp_row_sum(g_P1x, row, lane);
    float s2 = warp_row_sum(g_P2x, row, lane);
    if (lane == 0) {
        float t = softplus_f(__ldg(ltp));
        float dx = expf(-t * logf(s1));
        g_arow[row] = dx * rsqrtf(dx * s2);
    }
}

// ---------------------------------------------------------------------------
extern "C" void kernel_launch(void* const* d_in, const int* in_sizes, int n_in,
                              void* d_out, int out_size) {
    const float* X    = (const float*)d_in[0];
    const float* Xref = (const float*)d_in[1];
    const float* lep  = (const float*)d_in[2];
    const float* ltp  = (const float*)d_in[3];
    float* out = (float*)d_out;

    dim3 rgrid(NCT, NROWS / 256);
    const int rblocks = NROWS / 8;

    k_eval_sq<M_REF_SUM><<<NTRI, 256>>>(Xref, Xref, lep);             // 1
    k_dref<<<rblocks, 256>>>(ltp);                                    // 2
    k_eval_sq<M_REF_W><<<NTRI, 256>>>(Xref, Xref, lep);               // 3
    k_eval_rect<M_X_SUM><<<rgrid, 256>>>(X, Xref, lep, nullptr);      // 4  <- profiled
    k_bfin<<<rblocks, 256>>>();                                       // 5
    k_arow<<<rblocks, 256>>>(ltp);                                    // 6
    k_eval_rect<M_X_WRITE><<<rgrid, 256>>>(X, Xref, lep, out);        // 7
}

// round 16
// speedup vs baseline: 1.0311x; 1.0030x over previous
#include <cuda_runtime.h>
#include <cuda_bf16.h>
#include <cstdint>

#define NROWS 8192
#define DIM   16
#define NCT   64
#define NTRI  (NCT * (NCT + 1) / 2)   // 2080
#define LOG2E 1.4426950408889634f

typedef unsigned long long ull;

// ---- device scratch (static, no allocation) ----
__device__ float g_P1[NROWS * NCT];    // ref pass: sum K
__device__ float g_P2[NROWS * NCT];    // ref pass: sum K*Dref
__device__ float g_P1x[NROWS * NCT];   // x pass: sum K
__device__ float g_P2x[NROWS * NCT];   // x pass: sum K*Dref
__device__ float g_Dref[NROWS];
__device__ float g_bcol[NROWS];
__device__ float g_arow[NROWS];

__device__ __forceinline__ float ex2_approx(float x) {
    float r; asm("ex2.approx.f32 %0, %1;" : "=f"(r) : "f"(x)); return r;
}
__device__ __forceinline__ float softplus_f(float x) { return log1pf(expf(x)); }

// accumulate form: D += A*B (C == D)
__device__ __forceinline__ void mma16816(float& d0, float& d1, float& d2, float& d3,
                                         uint32_t a0, uint32_t a1, uint32_t a2, uint32_t a3,
                                         uint32_t b0, uint32_t b1) {
    asm volatile(
        "mma.sync.aligned.m16n8k16.row.col.f32.bf16.bf16.f32 "
        "{%0,%1,%2,%3}, {%4,%5,%6,%7}, {%8,%9}, {%0,%1,%2,%3};"
        : "+f"(d0), "+f"(d1), "+f"(d2), "+f"(d3)
        : "r"(a0), "r"(a1), "r"(a2), "r"(a3), "r"(b0), "r"(b1));
}

// zero-C form: D = A*B + (z,z,z,z)
__device__ __forceinline__ void mma16816_z(float& d0, float& d1, float& d2, float& d3,
                                           uint32_t a0, uint32_t a1, uint32_t a2, uint32_t a3,
                                           uint32_t b0, uint32_t b1, float z) {
    asm volatile(
        "mma.sync.aligned.m16n8k16.row.col.f32.bf16.bf16.f32 "
        "{%0,%1,%2,%3}, {%4,%5,%6,%7}, {%8,%9}, {%10,%10,%10,%10};"
        : "=f"(d0), "=f"(d1), "=f"(d2), "=f"(d3)
        : "r"(a0), "r"(a1), "r"(a2), "r"(a3), "r"(b0), "r"(b1), "f"(z));
}

// ---- packed f32x2 helpers ----
__device__ __forceinline__ ull dup2(float x) {
    ull r; asm("mov.b64 %0, {%1, %1};" : "=l"(r) : "f"(x)); return r;
}
__device__ __forceinline__ ull packf2(float lo, float hi) {
    ull r; asm("mov.b64 %0, {%1, %2};" : "=l"(r) : "f"(lo), "f"(hi)); return r;
}
__device__ __forceinline__ void unpackf2(ull v, float& lo, float& hi) {
    asm("mov.b64 {%0, %1}, %2;" : "=f"(lo), "=f"(hi) : "l"(v));
}
__device__ __forceinline__ ull mul2p(ull a, ull b) {
    ull d; asm("mul.rn.f32x2 %0, %1, %2;" : "=l"(d) : "l"(a), "l"(b)); return d;
}
__device__ __forceinline__ ull fma2p(ull a, ull b, ull c) {
    ull d; asm("fma.rn.f32x2 %0, %1, %2, %3;" : "=l"(d) : "l"(a), "l"(b), "l"(c)); return d;
}

// pack two floats into (hi bf16x2, lo bf16x2)
__device__ __forceinline__ uint2 pack_hilo(float x0, float x1) {
    uint32_t hw, lw;
    asm("cvt.rn.bf16x2.f32 %0, %2, %1;" : "=r"(hw) : "f"(x0), "f"(x1));
    float h0 = __bfloat162float(__ushort_as_bfloat16((unsigned short)(hw & 0xffffu)));
    float h1 = __bfloat162float(__ushort_as_bfloat16((unsigned short)(hw >> 16)));
    float l0 = x0 - h0;
    float l1 = x1 - h1;
    asm("cvt.rn.bf16x2.f32 %0, %2, %1;" : "=r"(lw) : "f"(l0), "f"(l1));
    uint2 r; r.x = hw; r.y = lw;
    return r;
}

#define M_REF_SUM 0
#define M_REF_W   1
#define M_X_SUM   2
#define M_X_WRITE 3

// ===========================================================================
// SQUARE symmetric kernel (ref passes) — exp-split epilogue (unchanged R15)
// ===========================================================================
template <int MODE>
__global__ void __launch_bounds__(256, 4)
k_eval_sq(const float* __restrict__ A,
          const float* __restrict__ B,
          const float* __restrict__ lep) {
    __shared__ uint4 sAf[128][4];
    __shared__ uint4 sBf[16][32];
    __shared__ float sEuA[128];
    __shared__ float sEv[128];
    __shared__ float sCw[128];
    __shared__ float sWa[128];
    __shared__ float sCol[8][128];

    int bx, by;
    {
        int l = blockIdx.x;
        bx = (int)((sqrtf(8.0f * (float)l + 1.0f) - 1.0f) * 0.5f);
        while ((bx * (bx + 1)) / 2 > l) bx--;
        while (((bx + 1) * (bx + 2)) / 2 <= l) bx++;
        by = l - (bx * (bx + 1)) / 2;
    }
    const bool offdiag = (by != bx);

    const int tid = threadIdx.x;
    const int w = tid >> 5;
    const int lane = tid & 31;
    const int g = lane >> 2;
    const int kq = lane & 3;
    const int rb = by * 128;
    const int cb = bx * 128;

    const float eps = softplus_f(__ldg(lep));
    const float twoc2 = 2.0f * LOG2E / (4.0f * eps);
    const float sc = sqrtf(twoc2);
    const float zf = 0.0f;

    {
        const int r = tid & 127;
        const bool isA = (tid < 128);
        const float4* s4 = reinterpret_cast<const float4*>(
            (isA ? A + (size_t)(rb + r) * DIM : B + (size_t)(cb + r) * DIM));
        float v[16]; float nrm = 0.0f;
#pragma unroll
        for (int q = 0; q < 4; q++) {
            float4 t = s4[q];
            v[4 * q] = t.x * sc; v[4 * q + 1] = t.y * sc;
            v[4 * q + 2] = t.z * sc; v[4 * q + 3] = t.w * sc;
            nrm += v[4 * q] * v[4 * q] + v[4 * q + 1] * v[4 * q + 1] +
                   v[4 * q + 2] * v[4 * q + 2] + v[4 * q + 3] * v[4 * q + 3];
        }
        uint2 p[8];
#pragma unroll
        for (int kp = 0; kp < 8; kp++) p[kp] = pack_hilo(v[2 * kp], v[2 * kp + 1]);
        const float E = ex2_approx(-0.5f * nrm);
        if (isA) {
#pragma unroll
            for (int q = 0; q < 4; q++)
                sAf[r][q] = make_uint4(p[q].x, p[q].y, p[q + 4].x, p[q + 4].y);
            sEuA[r] = E;
            if (MODE == M_REF_W) sWa[r] = g_Dref[rb + r];
        } else {
            const int bg = r & 7;
            const int bc8 = r >> 3;
#pragma unroll
            for (int q = 0; q < 4; q++)
                sBf[bc8][4 * bg + q] = make_uint4(p[q].x, p[q].y, p[q + 4].x, p[q + 4].y);
            sEv[r] = E;
            sCw[r] = (MODE == M_REF_W) ? E * g_Dref[cb + r] : E;
        }
    }
    __syncthreads();

    const int ra0 = w * 16 + g;
    const int ra1 = ra0 + 8;
    const uint4 af0 = sAf[ra0][kq];
    const uint4 af1 = sAf[ra1][kq];
    const float eu0 = sEuA[ra0];
    const float eu1 = sEuA[ra1];

    ull cr0p = 0, cr1p = 0;
    if (offdiag) {
        const float c0 = (MODE == M_REF_W) ? eu0 * sWa[ra0] : eu0;
        const float c1 = (MODE == M_REF_W) ? eu1 * sWa[ra1] : eu1;
        cr0p = dup2(c0);
        cr1p = dup2(c1);
    }

    ull s1a = 0, s1b = 0;

#pragma unroll
    for (int cb8 = 0; cb8 < 16; cb8++) {
        const uint4 bf = sBf[cb8][lane];
        const int cl = cb8 * 8 + 2 * kq;
        const ull cwp = *reinterpret_cast<const ull*>(&sCw[cl]);

        float d0, d1, d2, d3;
        mma16816_z(d0, d1, d2, d3, af0.x, af1.x, af0.z, af1.z, bf.x, bf.z, zf);
        mma16816(d0, d1, d2, d3, af0.x, af1.x, af0.z, af1.z, bf.y, bf.w);
        mma16816(d0, d1, d2, d3, af0.y, af1.y, af0.w, af1.w, bf.x, bf.z);

        const ull egp0 = packf2(ex2_approx(d0), ex2_approx(d1));
        const ull egp1 = packf2(ex2_approx(d2), ex2_approx(d3));

        s1a = fma2p(egp0, cwp, s1a);
        s1b = fma2p(egp1, cwp, s1b);

        if (offdiag) {
            ull cp = fma2p(egp1, cr1p, mul2p(egp0, cr0p));
            float c0, c1;
            unpackf2(cp, c0, c1);
#pragma unroll
            for (int off = 4; off <= 16; off <<= 1) {
                c0 += __shfl_xor_sync(0xffffffffu, c0, off);
                c1 += __shfl_xor_sync(0xffffffffu, c1, off);
            }
            if (g == 0) {
                sCol[w][cl] = c0;
                sCol[w][cl + 1] = c1;
            }
        }
    }

    {
        float x, y;
        unpackf2(s1a, x, y); float s1_0 = (x + y) * eu0;
        unpackf2(s1b, x, y); float s1_1 = (x + y) * eu1;
#pragma unroll
        for (int off = 1; off <= 2; off <<= 1) {
            s1_0 += __shfl_xor_sync(0xffffffffu, s1_0, off);
            s1_1 += __shfl_xor_sync(0xffffffffu, s1_1, off);
        }
        if (kq == 0) {
            if (MODE == M_REF_SUM) {
                g_P1[(size_t)(rb + ra0) * NCT + bx] = s1_0;
                g_P1[(size_t)(rb + ra1) * NCT + bx] = s1_1;
            } else {
                g_P2[(size_t)(rb + ra0) * NCT + bx] = s1_0;
                g_P2[(size_t)(rb + ra1) * NCT + bx] = s1_1;
            }
        }
    }

    if (offdiag) {
        __syncthreads();
        if (tid < 128) {
            float s = 0.0f;
#pragma unroll
            for (int q = 0; q < 8; q++) s += sCol[q][tid];
            s *= sEv[tid];
            if (MODE == M_REF_SUM) g_P1[(size_t)(cb + tid) * NCT + by] = s;
            else                   g_P2[(size_t)(cb + tid) * NCT + by] = s;
        }
    }
}

// ===========================================================================
// RECT kernel (X passes): 256x128; scalar chained accumulation (unchanged R15)
// ===========================================================================
template <int MODE>
__global__ void __launch_bounds__(256, 4)
k_eval_rect(const float* __restrict__ A,
            const float* __restrict__ B,
            const float* __restrict__ lep,
            float* __restrict__ out) {
    __shared__ uint4 sAf[256][4];
    __shared__ uint4 sBf[16][32];
    __shared__ float sEuA[256];
    __shared__ float sEv[128];
    __shared__ float sEw[128];
    __shared__ float sBc[128];

    const int tid = threadIdx.x;
    const int w = tid >> 5;
    const int lane = tid & 31;
    const int g = lane >> 2;
    const int kq = lane & 3;
    const int rb = blockIdx.y * 256;
    const int cb = blockIdx.x * 128;

    const float eps = softplus_f(__ldg(lep));
    const float twoc2 = 2.0f * LOG2E / (4.0f * eps);
    const float sc = sqrtf(twoc2);
    const float zf = 0.0f;

    {
        const float4* s4 = reinterpret_cast<const float4*>(A + (size_t)(rb + tid) * DIM);
        float v[16]; float nrm = 0.0f;
#pragma unroll
        for (int q = 0; q < 4; q++) {
            float4 t = s4[q];
            v[4 * q] = t.x * sc; v[4 * q + 1] = t.y * sc;
            v[4 * q + 2] = t.z * sc; v[4 * q + 3] = t.w * sc;
            nrm += v[4 * q] * v[4 * q] + v[4 * q + 1] * v[4 * q + 1] +
                   v[4 * q + 2] * v[4 * q + 2] + v[4 * q + 3] * v[4 * q + 3];
        }
        uint2 p[8];
#pragma unroll
        for (int kp = 0; kp < 8; kp++) p[kp] = pack_hilo(v[2 * kp], v[2 * kp + 1]);
#pragma unroll
        for (int q = 0; q < 4; q++)
            sAf[tid][q] = make_uint4(p[q].x, p[q].y, p[q + 4].x, p[q + 4].y);
        sEuA[tid] = ex2_approx(-0.5f * nrm);
    }
    if (tid < 128) {
        const float4* s4 = reinterpret_cast<const float4*>(B + (size_t)(cb + tid) * DIM);
        float v[16]; float nrm = 0.0f;
#pragma unroll
        for (int q = 0; q < 4; q++) {
            float4 t = s4[q];
            v[4 * q] = t.x * sc; v[4 * q + 1] = t.y * sc;
            v[4 * q + 2] = t.z * sc; v[4 * q + 3] = t.w * sc;
            nrm += v[4 * q] * v[4 * q] + v[4 * q + 1] * v[4 * q + 1] +
                   v[4 * q + 2] * v[4 * q + 2] + v[4 * q + 3] * v[4 * q + 3];
        }
        uint2 p[8];
#pragma unroll
        for (int kp = 0; kp < 8; kp++) p[kp] = pack_hilo(v[2 * kp], v[2 * kp + 1]);
        const int bg = tid & 7;
        const int bc8 = tid >> 3;
#pragma unroll
        for (int q = 0; q < 4; q++)
            sBf[bc8][4 * bg + q] = make_uint4(p[q].x, p[q].y, p[q + 4].x, p[q + 4].y);
        const float E = ex2_approx(-0.5f * nrm);
        sEv[tid] = E;
        if (MODE == M_X_SUM)   sEw[tid] = E * g_Dref[cb + tid];
        if (MODE == M_X_WRITE) sBc[tid] = E * g_bcol[cb + tid];
    }
    __syncthreads();

    const int ra0 = w * 32 + g;
    const int ra1 = ra0 + 8;
    const int ra2 = ra0 + 16;
    const int ra3 = ra0 + 24;
    const uint4 af0 = sAf[ra0][kq];
    const uint4 af1 = sAf[ra1][kq];
    const uint4 af2 = sAf[ra2][kq];
    const uint4 af3 = sAf[ra3][kq];
    const float eu0 = sEuA[ra0];
    const float eu1 = sEuA[ra1];
    const float eu2 = sEuA[ra2];
    const float eu3 = sEuA[ra3];

    ull rc0p = 0, rc1p = 0, rc2p = 0, rc3p = 0;
    if (MODE == M_X_WRITE) {
        rc0p = dup2(eu0 * g_arow[rb + ra0]);
        rc1p = dup2(eu1 * g_arow[rb + ra1]);
        rc2p = dup2(eu2 * g_arow[rb + ra2]);
        rc3p = dup2(eu3 * g_arow[rb + ra3]);
    }

    float s1[4] = {0.0f, 0.0f, 0.0f, 0.0f};
    float s2[4] = {0.0f, 0.0f, 0.0f, 0.0f};

#pragma unroll
    for (int cb8 = 0; cb8 < 16; cb8++) {
        const uint4 bf = sBf[cb8][lane];
        const int cl = cb8 * 8 + 2 * kq;

        float d0, d1, d2, d3, d4, d5, d6, d7;
        mma16816_z(d0, d1, d2, d3, af0.x, af1.x, af0.z, af1.z, bf.x, bf.z, zf);
        mma16816(d0, d1, d2, d3, af0.x, af1.x, af0.z, af1.z, bf.y, bf.w);
        mma16816(d0, d1, d2, d3, af0.y, af1.y, af0.w, af1.w, bf.x, bf.z);
        mma16816_z(d4, d5, d6, d7, af2.x, af3.x, af2.z, af3.z, bf.x, bf.z, zf);
        mma16816(d4, d5, d6, d7, af2.x, af3.x, af2.z, af3.z, bf.y, bf.w);
        mma16816(d4, d5, d6, d7, af2.y, af3.y, af2.w, af3.w, bf.x, bf.z);

        const float k0e = ex2_approx(d0), k0o = ex2_approx(d1);
        const float k1e = ex2_approx(d2), k1o = ex2_approx(d3);
        const float k2e = ex2_approx(d4), k2o = ex2_approx(d5);
        const float k3e = ex2_approx(d6), k3o = ex2_approx(d7);

        if (MODE == M_X_SUM) {
            const float2 ev = *reinterpret_cast<const float2*>(&sEv[cl]);
            const float2 ew = *reinterpret_cast<const float2*>(&sEw[cl]);
            s1[0] = fmaf(k0o, ev.y, fmaf(k0e, ev.x, s1[0]));
            s1[1] = fmaf(k1o, ev.y, fmaf(k1e, ev.x, s1[1]));
            s1[2] = fmaf(k2o, ev.y, fmaf(k2e, ev.x, s1[2]));
            s1[3] = fmaf(k3o, ev.y, fmaf(k3e, ev.x, s1[3]));
            s2[0] = fmaf(k0o, ew.y, fmaf(k0e, ew.x, s2[0]));
            s2[1] = fmaf(k1o, ew.y, fmaf(k1e, ew.x, s2[1]));
            s2[2] = fmaf(k2o, ew.y, fmaf(k2e, ew.x, s2[2]));
            s2[3] = fmaf(k3o, ew.y, fmaf(k3e, ew.x, s2[3]));
        } else { // M_X_WRITE
            const ull bcp = *reinterpret_cast<const ull*>(&sBc[cl]);
            ull o0 = mul2p(mul2p(packf2(k0e, k0o), bcp), rc0p);
            ull o1 = mul2p(mul2p(packf2(k1e, k1o), bcp), rc1p);
            ull o2 = mul2p(mul2p(packf2(k2e, k2o), bcp), rc2p);
            ull o3 = mul2p(mul2p(packf2(k3e, k3o), bcp), rc3p);
            *reinterpret_cast<ull*>(out + (size_t)(rb + ra0) * NROWS + cb + cl) = o0;
            *reinterpret_cast<ull*>(out + (size_t)(rb + ra1) * NROWS + cb + cl) = o1;
            *reinterpret_cast<ull*>(out + (size_t)(rb + ra2) * NROWS + cb + cl) = o2;
            *reinterpret_cast<ull*>(out + (size_t)(rb + ra3) * NROWS + cb + cl) = o3;
        }
    }

    if (MODE == M_X_SUM) {
        const float eus[4] = {eu0, eu1, eu2, eu3};
        float r1[4], r2[4];
#pragma unroll
        for (int i = 0; i < 4; i++) {
            r1[i] = s1[i] * eus[i];
            r2[i] = s2[i] * eus[i];
        }
#pragma unroll
        for (int off = 1; off <= 2; off <<= 1) {
#pragma unroll
            for (int i = 0; i < 4; i++) {
                r1[i] += __shfl_xor_sync(0xffffffffu, r1[i], off);
                r2[i] += __shfl_xor_sync(0xffffffffu, r2[i], off);
            }
        }
        if (kq == 0) {
            const int rows[4] = {ra0, ra1, ra2, ra3};
#pragma unroll
            for (int i = 0; i < 4; i++) {
                g_P1x[(size_t)(rb + rows[i]) * NCT + blockIdx.x] = r1[i];
                g_P2x[(size_t)(rb + rows[i]) * NCT + blockIdx.x] = r2[i];
            }
        }
    }
}

// ---------------------------------------------------------------------------
// warp-per-row reductions
// ---------------------------------------------------------------------------
__device__ __forceinline__ float warp_row_sum(const float* __restrict__ P,
                                              int row, int lane) {
    float2 p = reinterpret_cast<const float2*>(P + (size_t)row * NCT)[lane];
    float s = p.x + p.y;
#pragma unroll
    for (int off = 16; off >= 1; off >>= 1)
        s += __shfl_xor_sync(0xffffffffu, s, off);
    return s;
}

__global__ void k_dref(const float* __restrict__ ltp) {
    int row = blockIdx.x * 8 + (threadIdx.x >> 5);
    int lane = threadIdx.x & 31;
    float s = warp_row_sum(g_P1, row, lane);
    if (lane == 0) {
        float t = softplus_f(__ldg(ltp));
        g_Dref[row] = expf(-t * logf(s));
    }
}

__global__ void k_bfin() {
    int row = blockIdx.x * 8 + (threadIdx.x >> 5);
    int lane = threadIdx.x & 31;
    float T = warp_row_sum(g_P2, row, lane);
    if (lane == 0) {
        float dr = g_Dref[row];
        g_bcol[row] = dr * rsqrtf(dr * T);
    }
}

__global__ void k_arow(const float* __restrict__ ltp) {
    int row = blockIdx.x * 8 + (threadIdx.x >> 5);
    int lane = threadIdx.x & 31;
    float s1 = warp_row_sum(g_P1x, row, lane);
    float s2 = warp_row_sum(g_P2x, row, lane);
    if (lane == 0) {
        float t = softplus_f(__ldg(ltp));
        float dx = expf(-t * logf(s1));
        g_arow[row] = dx * rsqrtf(dx * s2);
    }
}

// ---------------------------------------------------------------------------
// Launcher with fork-join overlap: REF_W+bfin (per-thread stream) runs
// concurrently with X_SUM+arow (default stream). Events carry the deps;
// in non-captured execution the same edges enforce identical ordering.
// ---------------------------------------------------------------------------
extern "C" void kernel_launch(void* const* d_in, const int* in_sizes, int n_in,
                              void* d_out, int out_size) {
    const float* X    = (const float*)d_in[0];
    const float* Xref = (const float*)d_in[1];
    const float* lep  = (const float*)d_in[2];
    const float* ltp  = (const float*)d_in[3];
    float* out = (float*)d_out;

    dim3 rgrid(NCT, NROWS / 256);
    const int rblocks = NROWS / 8;

    cudaStream_t s2 = cudaStreamPerThread;
    cudaEvent_t evD, evB;
    cudaEventCreateWithFlags(&evD, cudaEventDisableTiming);
    cudaEventCreateWithFlags(&evB, cudaEventDisableTiming);

    // main stream: REF_SUM -> dref
    k_eval_sq<M_REF_SUM><<<NTRI, 256>>>(Xref, Xref, lep);
    k_dref<<<rblocks, 256>>>(ltp);
    cudaEventRecord(evD, 0);

    // fork: REF_W + bfin on per-thread stream (needs Dref only)
    cudaStreamWaitEvent(s2, evD, 0);
    k_eval_sq<M_REF_W><<<NTRI, 256, 0, s2>>>(Xref, Xref, lep);
    k_bfin<<<rblocks, 256, 0, s2>>>();
    cudaEventRecord(evB, s2);

    // main stream (concurrent): X_SUM + arow (needs Dref only)
    k_eval_rect<M_X_SUM><<<rgrid, 256>>>(X, Xref, lep, nullptr);
    k_arow<<<rblocks, 256>>>(ltp);

    // join: X_WRITE needs bcol (s2 branch) and arow (main branch)
    cudaStreamWaitEvent(0, evB, 0);
    k_eval_rect<M_X_WRITE><<<rgrid, 256>>>(X, Xref, lep, out);
}

// round 17
// speedup vs baseline: 1.0495x; 1.0179x over previous
#include <cuda_runtime.h>
#include <cuda_bf16.h>
#include <cstdint>

#define NROWS 8192
#define DIM   16
#define NCT   64
#define NTRI  (NCT * (NCT + 1) / 2)   // 2080
#define LOG2E 1.4426950408889634f

typedef unsigned long long ull;

// ---- device scratch (static, no allocation) ----
__device__ float g_P1[NROWS * NCT];    // ref pass: sum K
__device__ float g_P2[NROWS * NCT];    // ref pass: sum K*Dref
__device__ float g_P1x[NROWS * NCT];   // x pass: sum K
__device__ float g_P2x[NROWS * NCT];   // x pass: sum K*Dref
__device__ float g_Dref[NROWS];
__device__ float g_bcol[NROWS];
__device__ float g_arow[NROWS];

__device__ __forceinline__ float ex2_approx(float x) {
    float r; asm("ex2.approx.f32 %0, %1;" : "=f"(r) : "f"(x)); return r;
}
__device__ __forceinline__ float softplus_f(float x) { return log1pf(expf(x)); }

// accumulate form: D += A*B (C == D)
__device__ __forceinline__ void mma16816(float& d0, float& d1, float& d2, float& d3,
                                         uint32_t a0, uint32_t a1, uint32_t a2, uint32_t a3,
                                         uint32_t b0, uint32_t b1) {
    asm volatile(
        "mma.sync.aligned.m16n8k16.row.col.f32.bf16.bf16.f32 "
        "{%0,%1,%2,%3}, {%4,%5,%6,%7}, {%8,%9}, {%0,%1,%2,%3};"
        : "+f"(d0), "+f"(d1), "+f"(d2), "+f"(d3)
        : "r"(a0), "r"(a1), "r"(a2), "r"(a3), "r"(b0), "r"(b1));
}

// zero-C form: D = A*B + (z,z,z,z)
__device__ __forceinline__ void mma16816_z(float& d0, float& d1, float& d2, float& d3,
                                           uint32_t a0, uint32_t a1, uint32_t a2, uint32_t a3,
                                           uint32_t b0, uint32_t b1, float z) {
    asm volatile(
        "mma.sync.aligned.m16n8k16.row.col.f32.bf16.bf16.f32 "
        "{%0,%1,%2,%3}, {%4,%5,%6,%7}, {%8,%9}, {%10,%10,%10,%10};"
        : "=f"(d0), "=f"(d1), "=f"(d2), "=f"(d3)
        : "r"(a0), "r"(a1), "r"(a2), "r"(a3), "r"(b0), "r"(b1), "f"(z));
}

// ---- packed f32x2 helpers ----
__device__ __forceinline__ ull dup2(float x) {
    ull r; asm("mov.b64 %0, {%1, %1};" : "=l"(r) : "f"(x)); return r;
}
__device__ __forceinline__ ull packf2(float lo, float hi) {
    ull r; asm("mov.b64 %0, {%1, %2};" : "=l"(r) : "f"(lo), "f"(hi)); return r;
}
__device__ __forceinline__ void unpackf2(ull v, float& lo, float& hi) {
    asm("mov.b64 {%0, %1}, %2;" : "=f"(lo), "=f"(hi) : "l"(v));
}
__device__ __forceinline__ ull mul2p(ull a, ull b) {
    ull d; asm("mul.rn.f32x2 %0, %1, %2;" : "=l"(d) : "l"(a), "l"(b)); return d;
}
__device__ __forceinline__ ull fma2p(ull a, ull b, ull c) {
    ull d; asm("fma.rn.f32x2 %0, %1, %2, %3;" : "=l"(d) : "l"(a), "l"(b), "l"(c)); return d;
}

// pack two floats into (hi bf16x2, lo bf16x2)
__device__ __forceinline__ uint2 pack_hilo(float x0, float x1) {
    uint32_t hw, lw;
    asm("cvt.rn.bf16x2.f32 %0, %2, %1;" : "=r"(hw) : "f"(x0), "f"(x1));
    float h0 = __bfloat162float(__ushort_as_bfloat16((unsigned short)(hw & 0xffffu)));
    float h1 = __bfloat162float(__ushort_as_bfloat16((unsigned short)(hw >> 16)));
    float l0 = x0 - h0;
    float l1 = x1 - h1;
    asm("cvt.rn.bf16x2.f32 %0, %2, %1;" : "=r"(lw) : "f"(l0), "f"(l1));
    uint2 r; r.x = hw; r.y = lw;
    return r;
}

#define M_REF_SUM 0
#define M_REF_W   1
#define M_X_SUM   2
#define M_X_WRITE 3

// fragment layout (NEW): uint4 = (hi_kq, hi_kq+4, lo_kq, lo_kq+4)
// -> hi B-pair = (x,y) contiguous regs from LDS.128; lo pair = (z,w).

// ===========================================================================
// SQUARE symmetric kernel (ref passes)
// ===========================================================================
template <int MODE>
__global__ void __launch_bounds__(256, 4)
k_eval_sq(const float* __restrict__ A,
          const float* __restrict__ B,
          const float* __restrict__ lep) {
    __shared__ uint4 sAf[128][4];
    __shared__ uint4 sBf[16][32];
    __shared__ float sEuA[128];
    __shared__ float sEv[128];
    __shared__ float sCw[128];
    __shared__ float sWa[128];
    __shared__ float sCol[8][128];

    int bx, by;
    {
        int l = blockIdx.x;
        bx = (int)((sqrtf(8.0f * (float)l + 1.0f) - 1.0f) * 0.5f);
        while ((bx * (bx + 1)) / 2 > l) bx--;
        while (((bx + 1) * (bx + 2)) / 2 <= l) bx++;
        by = l - (bx * (bx + 1)) / 2;
    }
    const bool offdiag = (by != bx);

    const int tid = threadIdx.x;
    const int w = tid >> 5;
    const int lane = tid & 31;
    const int g = lane >> 2;
    const int kq = lane & 3;
    const int rb = by * 128;
    const int cb = bx * 128;

    const float eps = softplus_f(__ldg(lep));
    const float twoc2 = 2.0f * LOG2E / (4.0f * eps);
    const float sc = sqrtf(twoc2);
    const float zf = 0.0f;

    {
        const int r = tid & 127;
        const bool isA = (tid < 128);
        const float4* s4 = reinterpret_cast<const float4*>(
            (isA ? A + (size_t)(rb + r) * DIM : B + (size_t)(cb + r) * DIM));
        float v[16]; float nrm = 0.0f;
#pragma unroll
        for (int q = 0; q < 4; q++) {
            float4 t = s4[q];
            v[4 * q] = t.x * sc; v[4 * q + 1] = t.y * sc;
            v[4 * q + 2] = t.z * sc; v[4 * q + 3] = t.w * sc;
            nrm += v[4 * q] * v[4 * q] + v[4 * q + 1] * v[4 * q + 1] +
                   v[4 * q + 2] * v[4 * q + 2] + v[4 * q + 3] * v[4 * q + 3];
        }
        uint2 p[8];
#pragma unroll
        for (int kp = 0; kp < 8; kp++) p[kp] = pack_hilo(v[2 * kp], v[2 * kp + 1]);
        const float E = ex2_approx(-0.5f * nrm);
        if (isA) {
#pragma unroll
            for (int q = 0; q < 4; q++)
                sAf[r][q] = make_uint4(p[q].x, p[q + 4].x, p[q].y, p[q + 4].y);
            sEuA[r] = E;
            if (MODE == M_REF_W) sWa[r] = g_Dref[rb + r];
        } else {
            const int bg = r & 7;
            const int bc8 = r >> 3;
#pragma unroll
            for (int q = 0; q < 4; q++)
                sBf[bc8][4 * bg + q] = make_uint4(p[q].x, p[q + 4].x, p[q].y, p[q + 4].y);
            sEv[r] = E;
            sCw[r] = (MODE == M_REF_W) ? E * g_Dref[cb + r] : E;
        }
    }
    __syncthreads();

    const int ra0 = w * 16 + g;
    const int ra1 = ra0 + 8;
    const uint4 af0 = sAf[ra0][kq];   // (hi_kq, hi_kq4, lo_kq, lo_kq4)
    const uint4 af1 = sAf[ra1][kq];
    const float eu0 = sEuA[ra0];
    const float eu1 = sEuA[ra1];

    ull cr0p = 0, cr1p = 0;
    if (offdiag) {
        const float c0 = (MODE == M_REF_W) ? eu0 * sWa[ra0] : eu0;
        const float c1 = (MODE == M_REF_W) ? eu1 * sWa[ra1] : eu1;
        cr0p = dup2(c0);
        cr1p = dup2(c1);
    }

    ull s1a = 0, s1b = 0;

#pragma unroll
    for (int cb8 = 0; cb8 < 16; cb8++) {
        const uint4 bf = sBf[cb8][lane];  // (hi0, hi1, lo0, lo1)
        const int cl = cb8 * 8 + 2 * kq;
        const ull cwp = *reinterpret_cast<const ull*>(&sCw[cl]);

        float d0, d1, d2, d3;
        // hi*hi, hi*lo, lo*hi with contiguous operand pairs/quads
        mma16816_z(d0, d1, d2, d3, af0.x, af1.x, af0.y, af1.y, bf.x, bf.y, zf);
        mma16816(d0, d1, d2, d3, af0.x, af1.x, af0.y, af1.y, bf.z, bf.w);
        mma16816(d0, d1, d2, d3, af0.z, af1.z, af0.w, af1.w, bf.x, bf.y);

        const ull egp0 = packf2(ex2_approx(d0), ex2_approx(d1));
        const ull egp1 = packf2(ex2_approx(d2), ex2_approx(d3));

        s1a = fma2p(egp0, cwp, s1a);
        s1b = fma2p(egp1, cwp, s1b);

        if (offdiag) {
            ull cp = fma2p(egp1, cr1p, mul2p(egp0, cr0p));
            float c0, c1;
            unpackf2(cp, c0, c1);
#pragma unroll
            for (int off = 4; off <= 16; off <<= 1) {
                c0 += __shfl_xor_sync(0xffffffffu, c0, off);
                c1 += __shfl_xor_sync(0xffffffffu, c1, off);
            }
            if (g == 0) {
                sCol[w][cl] = c0;
                sCol[w][cl + 1] = c1;
            }
        }
    }

    {
        float x, y;
        unpackf2(s1a, x, y); float s1_0 = (x + y) * eu0;
        unpackf2(s1b, x, y); float s1_1 = (x + y) * eu1;
#pragma unroll
        for (int off = 1; off <= 2; off <<= 1) {
            s1_0 += __shfl_xor_sync(0xffffffffu, s1_0, off);
            s1_1 += __shfl_xor_sync(0xffffffffu, s1_1, off);
        }
        if (kq == 0) {
            if (MODE == M_REF_SUM) {
                g_P1[(size_t)(rb + ra0) * NCT + bx] = s1_0;
                g_P1[(size_t)(rb + ra1) * NCT + bx] = s1_1;
            } else {
                g_P2[(size_t)(rb + ra0) * NCT + bx] = s1_0;
                g_P2[(size_t)(rb + ra1) * NCT + bx] = s1_1;
            }
        }
    }

    if (offdiag) {
        __syncthreads();
        if (tid < 128) {
            float s = 0.0f;
#pragma unroll
            for (int q = 0; q < 8; q++) s += sCol[q][tid];
            s *= sEv[tid];
            if (MODE == M_REF_SUM) g_P1[(size_t)(cb + tid) * NCT + by] = s;
            else                   g_P2[(size_t)(cb + tid) * NCT + by] = s;
        }
    }
}

// ===========================================================================
// RECT kernel (X passes): 256x128
// ===========================================================================
template <int MODE>
__global__ void __launch_bounds__(256, 4)
k_eval_rect(const float* __restrict__ A,
            const float* __restrict__ B,
            const float* __restrict__ lep,
            float* __restrict__ out) {
    __shared__ uint4 sAf[256][4];
    __shared__ uint4 sBf[16][32];
    __shared__ float sEuA[256];
    __shared__ float sEv[128];
    __shared__ float sEw[128];
    __shared__ float sBc[128];

    const int tid = threadIdx.x;
    const int w = tid >> 5;
    const int lane = tid & 31;
    const int g = lane >> 2;
    const int kq = lane & 3;
    const int rb = blockIdx.y * 256;
    const int cb = blockIdx.x * 128;

    const float eps = softplus_f(__ldg(lep));
    const float twoc2 = 2.0f * LOG2E / (4.0f * eps);
    const float sc = sqrtf(twoc2);
    const float zf = 0.0f;

    {
        const float4* s4 = reinterpret_cast<const float4*>(A + (size_t)(rb + tid) * DIM);
        float v[16]; float nrm = 0.0f;
#pragma unroll
        for (int q = 0; q < 4; q++) {
            float4 t = s4[q];
            v[4 * q] = t.x * sc; v[4 * q + 1] = t.y * sc;
            v[4 * q + 2] = t.z * sc; v[4 * q + 3] = t.w * sc;
            nrm += v[4 * q] * v[4 * q] + v[4 * q + 1] * v[4 * q + 1] +
                   v[4 * q + 2] * v[4 * q + 2] + v[4 * q + 3] * v[4 * q + 3];
        }
        uint2 p[8];
#pragma unroll
        for (int kp = 0; kp < 8; kp++) p[kp] = pack_hilo(v[2 * kp], v[2 * kp + 1]);
#pragma unroll
        for (int q = 0; q < 4; q++)
            sAf[tid][q] = make_uint4(p[q].x, p[q + 4].x, p[q].y, p[q + 4].y);
        sEuA[tid] = ex2_approx(-0.5f * nrm);
    }
    if (tid < 128) {
        const float4* s4 = reinterpret_cast<const float4*>(B + (size_t)(cb + tid) * DIM);
        float v[16]; float nrm = 0.0f;
#pragma unroll
        for (int q = 0; q < 4; q++) {
            float4 t = s4[q];
            v[4 * q] = t.x * sc; v[4 * q + 1] = t.y * sc;
            v[4 * q + 2] = t.z * sc; v[4 * q + 3] = t.w * sc;
            nrm += v[4 * q] * v[4 * q] + v[4 * q + 1] * v[4 * q + 1] +
                   v[4 * q + 2] * v[4 * q + 2] + v[4 * q + 3] * v[4 * q + 3];
        }
        uint2 p[8];
#pragma unroll
        for (int kp = 0; kp < 8; kp++) p[kp] = pack_hilo(v[2 * kp], v[2 * kp + 1]);
        const int bg = tid & 7;
        const int bc8 = tid >> 3;
#pragma unroll
        for (int q = 0; q < 4; q++)
            sBf[bc8][4 * bg + q] = make_uint4(p[q].x, p[q + 4].x, p[q].y, p[q + 4].y);
        const float E = ex2_approx(-0.5f * nrm);
        sEv[tid] = E;
        if (MODE == M_X_SUM)   sEw[tid] = E * g_Dref[cb + tid];
        if (MODE == M_X_WRITE) sBc[tid] = E * g_bcol[cb + tid];
    }
    __syncthreads();

    const int ra0 = w * 32 + g;
    const int ra1 = ra0 + 8;
    const int ra2 = ra0 + 16;
    const int ra3 = ra0 + 24;
    const uint4 af0 = sAf[ra0][kq];
    const uint4 af1 = sAf[ra1][kq];
    const uint4 af2 = sAf[ra2][kq];
    const uint4 af3 = sAf[ra3][kq];
    const float eu0 = sEuA[ra0];
    const float eu1 = sEuA[ra1];
    const float eu2 = sEuA[ra2];
    const float eu3 = sEuA[ra3];

    ull rc0p = 0, rc1p = 0, rc2p = 0, rc3p = 0;
    if (MODE == M_X_WRITE) {
        rc0p = dup2(eu0 * g_arow[rb + ra0]);
        rc1p = dup2(eu1 * g_arow[rb + ra1]);
        rc2p = dup2(eu2 * g_arow[rb + ra2]);
        rc3p = dup2(eu3 * g_arow[rb + ra3]);
    }

    float s1[4] = {0.0f, 0.0f, 0.0f, 0.0f};
    float s2[4] = {0.0f, 0.0f, 0.0f, 0.0f};

#pragma unroll
    for (int cb8 = 0; cb8 < 16; cb8++) {
        const uint4 bf = sBf[cb8][lane];   // (hi0, hi1, lo0, lo1)
        const int cl = cb8 * 8 + 2 * kq;

        float d0, d1, d2, d3, d4, d5, d6, d7;
        mma16816_z(d0, d1, d2, d3, af0.x, af1.x, af0.y, af1.y, bf.x, bf.y, zf);
        mma16816(d0, d1, d2, d3, af0.x, af1.x, af0.y, af1.y, bf.z, bf.w);
        mma16816(d0, d1, d2, d3, af0.z, af1.z, af0.w, af1.w, bf.x, bf.y);
        mma16816_z(d4, d5, d6, d7, af2.x, af3.x, af2.y, af3.y, bf.x, bf.y, zf);
        mma16816(d4, d5, d6, d7, af2.x, af3.x, af2.y, af3.y, bf.z, bf.w);
        mma16816(d4, d5, d6, d7, af2.z, af3.z, af2.w, af3.w, bf.x, bf.y);

        const float k0e = ex2_approx(d0), k0o = ex2_approx(d1);
        const float k1e = ex2_approx(d2), k1o = ex2_approx(d3);
        const float k2e = ex2_approx(d4), k2o = ex2_approx(d5);
        const float k3e = ex2_approx(d6), k3o = ex2_approx(d7);

        if (MODE == M_X_SUM) {
            const float2 ev = *reinterpret_cast<const float2*>(&sEv[cl]);
            const float2 ew = *reinterpret_cast<const float2*>(&sEw[cl]);
            s1[0] = fmaf(k0o, ev.y, fmaf(k0e, ev.x, s1[0]));
            s1[1] = fmaf(k1o, ev.y, fmaf(k1e, ev.x, s1[1]));
            s1[2] = fmaf(k2o, ev.y, fmaf(k2e, ev.x, s1[2]));
            s1[3] = fmaf(k3o, ev.y, fmaf(k3e, ev.x, s1[3]));
            s2[0] = fmaf(k0o, ew.y, fmaf(k0e, ew.x, s2[0]));
            s2[1] = fmaf(k1o, ew.y, fmaf(k1e, ew.x, s2[1]));
            s2[2] = fmaf(k2o, ew.y, fmaf(k2e, ew.x, s2[2]));
            s2[3] = fmaf(k3o, ew.y, fmaf(k3e, ew.x, s2[3]));
        } else { // M_X_WRITE
            const ull bcp = *reinterpret_cast<const ull*>(&sBc[cl]);
            ull o0 = mul2p(mul2p(packf2(k0e, k0o), bcp), rc0p);
            ull o1 = mul2p(mul2p(packf2(k1e, k1o), bcp), rc1p);
            ull o2 = mul2p(mul2p(packf2(k2e, k2o), bcp), rc2p);
            ull o3 = mul2p(mul2p(packf2(k3e, k3o), bcp), rc3p);
            *reinterpret_cast<ull*>(out + (size_t)(rb + ra0) * NROWS + cb + cl) = o0;
            *reinterpret_cast<ull*>(out + (size_t)(rb + ra1) * NROWS + cb + cl) = o1;
            *reinterpret_cast<ull*>(out + (size_t)(rb + ra2) * NROWS + cb + cl) = o2;
            *reinterpret_cast<ull*>(out + (size_t)(rb + ra3) * NROWS + cb + cl) = o3;
        }
    }

    if (MODE == M_X_SUM) {
        const float eus[4] = {eu0, eu1, eu2, eu3};
        float r1[4], r2[4];
#pragma unroll
        for (int i = 0; i < 4; i++) {
            r1[i] = s1[i] * eus[i];
            r2[i] = s2[i] * eus[i];
        }
#pragma unroll
        for (int off = 1; off <= 2; off <<= 1) {
#pragma unroll
            for (int i = 0; i < 4; i++) {
                r1[i] += __shfl_xor_sync(0xffffffffu, r1[i], off);
                r2[i] += __shfl_xor_sync(0xffffffffu, r2[i], off);
            }
        }
        if (kq == 0) {
            const int rows[4] = {ra0, ra1, ra2, ra3};
#pragma unroll
            for (int i = 0; i < 4; i++) {
                g_P1x[(size_t)(rb + rows[i]) * NCT + blockIdx.x] = r1[i];
                g_P2x[(size_t)(rb + rows[i]) * NCT + blockIdx.x] = r2[i];
            }
        }
    }
}

// ---------------------------------------------------------------------------
// warp-per-row reductions
// ---------------------------------------------------------------------------
__device__ __forceinline__ float warp_row_sum(const float* __restrict__ P,
                                              int row, int lane) {
    float2 p = reinterpret_cast<const float2*>(P + (size_t)row * NCT)[lane];
    float s = p.x + p.y;
#pragma unroll
    for (int off = 16; off >= 1; off >>= 1)
        s += __shfl_xor_sync(0xffffffffu, s, off);
    return s;
}

__global__ void k_dref(const float* __restrict__ ltp) {
    int row = blockIdx.x * 8 + (threadIdx.x >> 5);
    int lane = threadIdx.x & 31;
    float s = warp_row_sum(g_P1, row, lane);
    if (lane == 0) {
        float t = softplus_f(__ldg(ltp));
        g_Dref[row] = expf(-t * logf(s));
    }
}

__global__ void k_bfin() {
    int row = blockIdx.x * 8 + (threadIdx.x >> 5);
    int lane = threadIdx.x & 31;
    float T = warp_row_sum(g_P2, row, lane);
    if (lane == 0) {
        float dr = g_Dref[row];
        g_bcol[row] = dr * rsqrtf(dr * T);
    }
}

__global__ void k_arow(const float* __restrict__ ltp) {
    int row = blockIdx.x * 8 + (threadIdx.x >> 5);
    int lane = threadIdx.x & 31;
    float s1 = warp_row_sum(g_P1x, row, lane);
    float s2 = warp_row_sum(g_P2x, row, lane);
    if (lane == 0) {
        float t = softplus_f(__ldg(ltp));
        float dx = expf(-t * logf(s1));
        g_arow[row] = dx * rsqrtf(dx * s2);
    }
}

// ---------------------------------------------------------------------------
// Launcher with fork-join overlap (same as R16)
// ---------------------------------------------------------------------------
extern "C" void kernel_launch(void* const* d_in, const int* in_sizes, int n_in,
                              void* d_out, int out_size) {
    const float* X    = (const float*)d_in[0];
    const float* Xref = (const float*)d_in[1];
    const float* lep  = (const float*)d_in[2];
    const float* ltp  = (const float*)d_in[3];
    float* out = (float*)d_out;

    dim3 rgrid(NCT, NROWS / 256);
    const int rblocks = NROWS / 8;

    cudaStream_t s2 = cudaStreamPerThread;
    cudaEvent_t evD, evB;
    cudaEventCreateWithFlags(&evD, cudaEventDisableTiming);
    cudaEventCreateWithFlags(&evB, cudaEventDisableTiming);

    // main stream: REF_SUM -> dref
    k_eval_sq<M_REF_SUM><<<NTRI, 256>>>(Xref, Xref, lep);
    k_dref<<<rblocks, 256>>>(ltp);
    cudaEventRecord(evD, 0);

    // fork: REF_W + bfin on per-thread stream (needs Dref only)
    cudaStreamWaitEvent(s2, evD, 0);
    k_eval_sq<M_REF_W><<<NTRI, 256, 0, s2>>>(Xref, Xref, lep);
    k_bfin<<<rblocks, 256, 0, s2>>>();
    cudaEventRecord(evB, s2);

    // main stream (concurrent): X_SUM + arow (needs Dref only)
    k_eval_rect<M_X_SUM><<<rgrid, 256>>>(X, Xref, lep, nullptr);
    k_arow<<<rblocks, 256>>>(ltp);

    // join: X_WRITE needs bcol (s2 branch) and arow (main branch)
    cudaStreamWaitEvent(0, evB, 0);
    k_eval_rect<M_X_WRITE><<<rgrid, 256>>>(X, Xref, lep, out);
}